// round 4
// baseline (speedup 1.0000x reference)
#include <cuda_runtime.h>

// Problem constants
constexpr int B  = 4;
constexpr int N  = 2048;
constexpr int D  = 1024;
constexpr int H  = 16;
constexpr int DH = 64;
constexpr int M  = B * N;   // 8192

// Scratch (device globals; referenced DIRECTLY from device code).
__device__ float g_q[M * D];     // [b,h,n,dh], pre-scaled by 1/sqrt(DH)
__device__ float g_k[M * D];     // [b,h,n,dh]
__device__ float g_v[M * D];     // [b,h,n,dh]
__device__ float g_attn[M * D];  // [b,n,d] merged heads

// XOR swizzles for conflict-free LDS.128.
__device__ __forceinline__ int swz32(int row, int g) {  // g = col/4, 0..7
    return row * 32 + ((g ^ ((row >> 3) & 7)) << 2);
}
__device__ __forceinline__ int swz64(int row, int g) {  // g = col/4, 0..15
    return row * 64 + ((g ^ ((row >> 2) & 7)) << 2);
}

// ---------------------------------------------------------------------------
// GEMM (NT): C[m,e] = scale * sum_d A[m,d] * W[e,d]
// Tile 128x128, BK=32, 256 threads, 8x8 per thread.
// mode 0/1/2: A = x param, C = g_q/g_k/g_v in [b,h,n,dh] split layout.
// mode 3:     A = g_attn (device global), C = Cout param, plain [m,e].
// ---------------------------------------------------------------------------
__global__ void __launch_bounds__(256) gemm128(
    const float* __restrict__ A_in, const float* __restrict__ W,
    float* __restrict__ Cout, float scale, int mode)
{
    __shared__ __align__(16) float As[128 * 32];
    __shared__ __align__(16) float Bs[128 * 32];

    const float* A = (mode == 3) ? (const float*)g_attn : A_in;
    float* C;
    if      (mode == 0) C = g_q;
    else if (mode == 1) C = g_k;
    else if (mode == 2) C = g_v;
    else                C = Cout;

    const int tid = threadIdx.x;
    const int m0  = blockIdx.x * 128;
    const int e0  = blockIdx.y * 128;
    const int r0  = (tid >> 4) << 3;   // 0..120
    const int c0  = (tid & 15) << 3;   // 0..120

    float acc[8][8];
    #pragma unroll
    for (int i = 0; i < 8; i++)
        #pragma unroll
        for (int j = 0; j < 8; j++) acc[i][j] = 0.f;

    for (int k0 = 0; k0 < D; k0 += 32) {
        // 128 rows x 8 float4-groups = 1024 float4 per tile -> 4 per thread.
        #pragma unroll
        for (int t = 0; t < 4; t++) {
            int idx = tid + t * 256;        // 0..1023
            int row = idx >> 3;             // 0..127
            int g   = idx & 7;
            *(float4*)&As[swz32(row, g)] =
                *(const float4*)&A[(size_t)(m0 + row) * D + k0 + (g << 2)];
            *(float4*)&Bs[swz32(row, g)] =
                *(const float4*)&W[(size_t)(e0 + row) * D + k0 + (g << 2)];
        }
        __syncthreads();

        #pragma unroll
        for (int kk = 0; kk < 32; kk += 4) {
            const int g = kk >> 2;
            float4 a[8], b[8];
            #pragma unroll
            for (int i = 0; i < 8; i++) a[i] = *(const float4*)&As[swz32(r0 + i, g)];
            #pragma unroll
            for (int j = 0; j < 8; j++) b[j] = *(const float4*)&Bs[swz32(c0 + j, g)];
            #pragma unroll
            for (int i = 0; i < 8; i++)
                #pragma unroll
                for (int j = 0; j < 8; j++)
                    acc[i][j] += a[i].x * b[j].x + a[i].y * b[j].y
                               + a[i].z * b[j].z + a[i].w * b[j].w;
        }
        __syncthreads();
    }

    #pragma unroll
    for (int i = 0; i < 8; i++) {
        const int m  = m0 + r0 + i;
        const int bb = m >> 11;        // m / N
        const int nn = m & (N - 1);
        #pragma unroll
        for (int j4 = 0; j4 < 8; j4 += 4) {
            const int e = e0 + c0 + j4;
            float4 v = make_float4(acc[i][j4 + 0] * scale, acc[i][j4 + 1] * scale,
                                   acc[i][j4 + 2] * scale, acc[i][j4 + 3] * scale);
            if (mode != 3) {
                const int h = e >> 6, dh = e & 63;
                *(float4*)&C[(((size_t)(bb * H + h)) * N + nn) * DH + dh] = v;
            } else {
                *(float4*)&C[(size_t)m * D + e] = v;
            }
        }
    }
}

// ---------------------------------------------------------------------------
// Flash attention, fp32. Block: 64 query rows, softmax over N keys in
// 64-key tiles. 256 threads, 4 rows x 4 dh cols per thread.
// Static shared = 48KB. P tile reuses the K buffer.
// Reads g_q/g_k/g_v, writes g_attn — all device globals, no params.
// ---------------------------------------------------------------------------
__global__ void __launch_bounds__(256) attn_kernel()
{
    __shared__ __align__(16) float Qs [64 * 64];
    __shared__ __align__(16) float KPs[64 * 64];   // K tile, then P tile
    __shared__ __align__(16) float Vs [64 * 64];

    const int tid = threadIdx.x;
    const int bh  = blockIdx.y;                  // b*H + h
    const int n0  = blockIdx.x * 64;
    const float* Qb = g_q + (size_t)bh * N * DH;
    const float* Kb = g_k + (size_t)bh * N * DH;
    const float* Vb = g_v + (size_t)bh * N * DH;

    const int r0 = (tid >> 4) << 2;   // 0..60  (query rows)
    const int c0 = (tid & 15) << 2;   // 0..60  (key col / dh col)

    // Load Q tile once (64x64 = 1024 float4, 4 per thread)
    #pragma unroll
    for (int t = 0; t < 4; t++) {
        int idx = tid + t * 256;      // 0..1023
        int row = idx >> 4;           // 0..63
        int g   = idx & 15;
        *(float4*)&Qs[swz64(row, g)] =
            *(const float4*)&Qb[(size_t)(n0 + row) * DH + (g << 2)];
    }

    float mI[4], lI[4], o[4][4];
    #pragma unroll
    for (int i = 0; i < 4; i++) {
        mI[i] = -1e30f; lI[i] = 0.f;
        #pragma unroll
        for (int j = 0; j < 4; j++) o[i][j] = 0.f;
    }

    for (int kt = 0; kt < N; kt += 64) {
        __syncthreads();   // previous-iteration readers of KPs/Vs done
        #pragma unroll
        for (int t = 0; t < 4; t++) {
            int idx = tid + t * 256;  // 0..1023
            int row = idx >> 4;       // 0..63
            int g   = idx & 15;
            *(float4*)&KPs[swz64(row, g)] =
                *(const float4*)&Kb[(size_t)(kt + row) * DH + (g << 2)];
            *(float4*)&Vs[swz64(row, g)] =
                *(const float4*)&Vb[(size_t)(kt + row) * DH + (g << 2)];
        }
        __syncthreads();

        // S = Q_tile @ K_tile^T   (4x4 per thread)
        float s[4][4];
        #pragma unroll
        for (int i = 0; i < 4; i++)
            #pragma unroll
            for (int j = 0; j < 4; j++) s[i][j] = 0.f;

        #pragma unroll
        for (int kk = 0; kk < 64; kk += 4) {
            const int g = kk >> 2;
            float4 a[4], bq[4];
            #pragma unroll
            for (int i = 0; i < 4; i++) a[i]  = *(const float4*)&Qs[swz64(r0 + i, g)];
            #pragma unroll
            for (int j = 0; j < 4; j++) bq[j] = *(const float4*)&KPs[swz64(c0 + j, g)];
            #pragma unroll
            for (int i = 0; i < 4; i++)
                #pragma unroll
                for (int j = 0; j < 4; j++)
                    s[i][j] += a[i].x * bq[j].x + a[i].y * bq[j].y
                             + a[i].z * bq[j].z + a[i].w * bq[j].w;
        }

        // Online softmax; row stats reduced across the 16 lanes sharing r0.
        #pragma unroll
        for (int i = 0; i < 4; i++) {
            float mx = fmaxf(fmaxf(s[i][0], s[i][1]), fmaxf(s[i][2], s[i][3]));
            mx = fmaxf(mx, __shfl_xor_sync(0xffffffffu, mx, 1));
            mx = fmaxf(mx, __shfl_xor_sync(0xffffffffu, mx, 2));
            mx = fmaxf(mx, __shfl_xor_sync(0xffffffffu, mx, 4));
            mx = fmaxf(mx, __shfl_xor_sync(0xffffffffu, mx, 8));
            const float mnew = fmaxf(mI[i], mx);
            const float corr = __expf(mI[i] - mnew);
            mI[i] = mnew;
            float rs = 0.f;
            #pragma unroll
            for (int j = 0; j < 4; j++) {
                s[i][j] = __expf(s[i][j] - mnew);
                rs += s[i][j];
            }
            rs += __shfl_xor_sync(0xffffffffu, rs, 1);
            rs += __shfl_xor_sync(0xffffffffu, rs, 2);
            rs += __shfl_xor_sync(0xffffffffu, rs, 4);
            rs += __shfl_xor_sync(0xffffffffu, rs, 8);
            lI[i] = lI[i] * corr + rs;
            #pragma unroll
            for (int j = 0; j < 4; j++) o[i][j] *= corr;
        }

        __syncthreads();   // everyone done READING K before overwriting with P
        #pragma unroll
        for (int i = 0; i < 4; i++)
            *(float4*)&KPs[swz64(r0 + i, c0 >> 2)] =
                make_float4(s[i][0], s[i][1], s[i][2], s[i][3]);
        __syncthreads();

        // O += P @ V   (4x4 per thread, dh block = c0)
        #pragma unroll
        for (int c = 0; c < 64; c += 4) {
            float4 p[4], vv[4];
            #pragma unroll
            for (int i = 0; i < 4; i++) p[i]  = *(const float4*)&KPs[swz64(r0 + i, c >> 2)];
            #pragma unroll
            for (int t = 0; t < 4; t++) vv[t] = *(const float4*)&Vs[swz64(c + t, c0 >> 2)];
            #pragma unroll
            for (int i = 0; i < 4; i++) {
                o[i][0] += p[i].x * vv[0].x + p[i].y * vv[1].x + p[i].z * vv[2].x + p[i].w * vv[3].x;
                o[i][1] += p[i].x * vv[0].y + p[i].y * vv[1].y + p[i].z * vv[2].y + p[i].w * vv[3].y;
                o[i][2] += p[i].x * vv[0].z + p[i].y * vv[1].z + p[i].z * vv[2].z + p[i].w * vv[3].z;
                o[i][3] += p[i].x * vv[0].w + p[i].y * vv[1].w + p[i].z * vv[2].w + p[i].w * vv[3].w;
            }
        }
    }

    // Normalize and write merged-heads layout [b, n, h*DH + dh]
    const int bb = bh / H, hh = bh % H;
    #pragma unroll
    for (int i = 0; i < 4; i++) {
        const float inv = 1.f / lI[i];
        const int n = n0 + r0 + i;
        float4 v = make_float4(o[i][0] * inv, o[i][1] * inv,
                               o[i][2] * inv, o[i][3] * inv);
        *(float4*)&g_attn[((size_t)(bb * N + n)) * D + hh * DH + c0] = v;
    }
}

// ---------------------------------------------------------------------------
// kernel_launch. Inputs identified by element count:
//   x = M*D = 8388608 elems; weights = D*D = 1048576 elems each,
//   in order of appearance (Wq, Wk, Wv, Wo). mask (8192) ignored.
// ---------------------------------------------------------------------------
extern "C" void kernel_launch(void* const* d_in, const int* in_sizes, int n_in,
                              void* d_out, int out_size) {
    (void)out_size;
    const float* x = nullptr;
    const float* Wt[4] = {nullptr, nullptr, nullptr, nullptr};
    int c = 0;
    for (int i = 0; i < n_in; i++) {
        if (in_sizes[i] == M * D && !x) x = (const float*)d_in[i];
        else if (in_sizes[i] == D * D && c < 4) Wt[c++] = (const float*)d_in[i];
    }
    float* out = (float*)d_out;

    dim3 gg(M / 128, D / 128);   // (64, 8)
    gemm128<<<gg, 256>>>(x, Wt[0], nullptr, 0.125f, 0);  // Q (1/sqrt(DH) folded)
    gemm128<<<gg, 256>>>(x, Wt[1], nullptr, 1.0f,   1);  // K
    gemm128<<<gg, 256>>>(x, Wt[2], nullptr, 1.0f,   2);  // V

    attn_kernel<<<dim3(N / 64, B * H), 256>>>();

    gemm128<<<gg, 256>>>(nullptr, Wt[3], out, 1.0f, 3);  // Wo projection
}

// round 6
// speedup vs baseline: 1.4427x; 1.4427x over previous
#include <cuda_runtime.h>
#include <cuda_bf16.h>
#include <cstdint>

// Problem constants
constexpr int B  = 4;
constexpr int N  = 2048;
constexpr int D  = 1024;
constexpr int H  = 16;
constexpr int DH = 64;
constexpr int M  = B * N;   // 8192

// Scratch (device globals; referenced directly from device code).
__device__ float g_q[M * D];     // [b,h,n,dh], pre-scaled by 1/sqrt(DH)
__device__ float g_k[M * D];     // [b,h,n,dh]
__device__ float g_v[M * D];     // [b,h,n,dh]
__device__ float g_attn[M * D];  // [b,n,d] merged heads

__device__ __forceinline__ uint32_t smem_u32(const void* p) {
    uint32_t a;
    asm("{ .reg .u64 t; cvta.to.shared.u64 t, %1; cvt.u32.u64 %0, t; }"
        : "=r"(a) : "l"(p));
    return a;
}
__device__ __forceinline__ uint32_t swz128(uint32_t off) {
    return off ^ ((off >> 3) & 0x70);
}

#define LDSM4(r0, r1, r2, r3, a)                                            \
    asm volatile("ldmatrix.sync.aligned.m8n8.x4.shared.b16 "                \
                 "{%0,%1,%2,%3}, [%4];"                                     \
                 : "=r"(r0), "=r"(r1), "=r"(r2), "=r"(r3) : "r"(a))

#define MMA16816(c, a, b)                                                   \
    asm volatile("mma.sync.aligned.m16n8k16.row.col.f32.bf16.bf16.f32 "     \
                 "{%0,%1,%2,%3}, {%4,%5,%6,%7}, {%8,%9}, {%0,%1,%2,%3};"    \
                 : "+f"((c)[0]), "+f"((c)[1]), "+f"((c)[2]), "+f"((c)[3])   \
                 : "r"((a)[0]), "r"((a)[1]), "r"((a)[2]), "r"((a)[3]),      \
                   "r"((b)[0]), "r"((b)[1]))

// Split 8 fp32 into packed bf16 hi / lo pairs (2-term compensation).
__device__ __forceinline__ void split8(const float4 u, const float4 v,
                                       uint32_t* hi, uint32_t* lo)
{
    float f[8] = { u.x, u.y, u.z, u.w, v.x, v.y, v.z, v.w };
    #pragma unroll
    for (int p = 0; p < 4; p++) {
        __nv_bfloat162 h = __floats2bfloat162_rn(f[2*p], f[2*p+1]);
        float2 hf = __bfloat1622float2(h);
        __nv_bfloat162 l = __floats2bfloat162_rn(f[2*p]   - hf.x,
                                                 f[2*p+1] - hf.y);
        hi[p] = *(uint32_t*)&h;
        lo[p] = *(uint32_t*)&l;
    }
}

// ---------------------------------------------------------------------------
// Tensor-core GEMM (NT) via mma.sync bf16 + 2-term split compensation.
// C[m,e] = scale * sum_d A[m,d] * W[e,d] ;  D = Ah*Bh + Ah*Bl + Al*Bh (fp32 acc)
// CTA tile 128x128, BK=32, 256 threads = 8 warps (2 M x 4 N), warp tile 64x32.
// SMEM row (128B, SW128-swizzled): [hi: 32 bf16 | lo: 32 bf16].
// mode 0/1/2: A = x param, C = g_q/g_k/g_v split-head layout. mode 3: g_attn->Cout.
// ---------------------------------------------------------------------------
__global__ void __launch_bounds__(256) gemm_mma(
    const float* __restrict__ A_in, const float* __restrict__ W,
    float* __restrict__ Cout, float scale, int mode)
{
    __shared__ __align__(128) char smA[128 * 128];   // 16KB
    __shared__ __align__(128) char smB[128 * 128];   // 16KB

    const float* A = (mode == 3) ? (const float*)g_attn : A_in;
    float* C;
    if      (mode == 0) C = g_q;
    else if (mode == 1) C = g_k;
    else if (mode == 2) C = g_v;
    else                C = Cout;

    const int tid   = threadIdx.x;
    const int lane  = tid & 31;
    const int wid   = tid >> 5;
    const int wm    = (wid >> 2) * 64;   // warp M offset (0/64)
    const int wn    = (wid & 3) * 32;    // warp N offset (0/32/64/96)
    const int m0    = blockIdx.x * 128;
    const int e0    = blockIdx.y * 128;

    const uint32_t uA = smem_u32(smA);
    const uint32_t uB = smem_u32(smB);

    // Loader mapping: thread -> (row, k-half)
    const int lrow  = tid >> 1;          // 0..127
    const int lhalf = tid & 1;           // 0/1 -> k 0..15 / 16..31

    float acc[4][4][4];                  // [mtile][ntile][frag]
    #pragma unroll
    for (int i = 0; i < 4; i++)
        #pragma unroll
        for (int j = 0; j < 4; j++)
            #pragma unroll
            for (int f = 0; f < 4; f++) acc[i][j][f] = 0.f;

    // Precompute per-lane ldmatrix byte offsets (swizzle applied per access).
    const int q  = lane >> 3;            // matrix index 0..3
    const int r8 = lane & 7;             // row within 8x8 matrix
    // A (16x16): matrices {rows0-7,k0-7},{rows8-15,k0-7},{rows0-7,k8-15},{rows8-15,k8-15}
    const int a_row_in = (q & 1) * 8 + r8;
    const int a_kb     = (q >> 1) * 16;
    // B pair (two 8-row n-tiles): {tile j,k0-7},{tile j,k8-15},{tile j+1,k0-7},{tile j+1,k8-15}
    const int b_tile_in = (q >> 1);      // 0/1 within pair
    const int b_kb      = (q & 1) * 16;

    for (int kc = 0; kc < D / 32; kc++) {
        const int k0 = kc * 32;

        // Prefetch this chunk's global data (16 floats of A, 16 of B).
        float4 ra[4], rb[4];
        const float4* arow = (const float4*)&A[(size_t)(m0 + lrow) * D + k0] + lhalf * 4;
        const float4* brow = (const float4*)&W[(size_t)(e0 + lrow) * D + k0] + lhalf * 4;
        #pragma unroll
        for (int g4 = 0; g4 < 4; g4++) { ra[g4] = arow[g4]; rb[g4] = brow[g4]; }

        __syncthreads();   // previous chunk's ldmatrix reads complete

        // Split-convert and store. hi at row bytes [0,64), lo at [64,128).
        {
            uint32_t hi[8], lo[8];
            split8(ra[0], ra[1], hi,     lo);
            split8(ra[2], ra[3], hi + 4, lo + 4);
            const uint32_t rbyte = lrow * 128 + lhalf * 32;
            *(uint4*)(smA + swz128(rbyte))           = *(uint4*)(hi);
            *(uint4*)(smA + swz128(rbyte + 16))      = *(uint4*)(hi + 4);
            *(uint4*)(smA + swz128(rbyte + 64))      = *(uint4*)(lo);
            *(uint4*)(smA + swz128(rbyte + 64 + 16)) = *(uint4*)(lo + 4);

            split8(rb[0], rb[1], hi,     lo);
            split8(rb[2], rb[3], hi + 4, lo + 4);
            *(uint4*)(smB + swz128(rbyte))           = *(uint4*)(hi);
            *(uint4*)(smB + swz128(rbyte + 16))      = *(uint4*)(hi + 4);
            *(uint4*)(smB + swz128(rbyte + 64))      = *(uint4*)(lo);
            *(uint4*)(smB + swz128(rbyte + 64 + 16)) = *(uint4*)(lo + 4);
        }
        __syncthreads();

        #pragma unroll
        for (int s = 0; s < 2; s++) {    // two K=16 steps per chunk
            uint32_t ah[4][4], al[4][4], bh[4][2], bl[4][2];

            #pragma unroll
            for (int i = 0; i < 4; i++) {
                const uint32_t rowb = (wm + i * 16 + a_row_in) * 128 + s * 32 + a_kb;
                LDSM4(ah[i][0], ah[i][1], ah[i][2], ah[i][3], uA + swz128(rowb));
                LDSM4(al[i][0], al[i][1], al[i][2], al[i][3], uA + swz128(rowb + 64));
            }
            #pragma unroll
            for (int jp = 0; jp < 2; jp++) {   // n-tile pairs {0,1},{2,3}
                const uint32_t rowb =
                    (wn + (jp * 2 + b_tile_in) * 8 + r8) * 128 + s * 32 + b_kb;
                LDSM4(bh[2*jp][0], bh[2*jp][1], bh[2*jp+1][0], bh[2*jp+1][1],
                      uB + swz128(rowb));
                LDSM4(bl[2*jp][0], bl[2*jp][1], bl[2*jp+1][0], bl[2*jp+1][1],
                      uB + swz128(rowb + 64));
            }

            #pragma unroll
            for (int i = 0; i < 4; i++)
                #pragma unroll
                for (int j = 0; j < 4; j++) {
                    MMA16816(acc[i][j], ah[i], bh[j]);   // Ah*Bh
                    MMA16816(acc[i][j], ah[i], bl[j]);   // Ah*Bl
                    MMA16816(acc[i][j], al[i], bh[j]);   // Al*Bh
                }
        }
    }

    // Epilogue. Fragment c0,c1 -> (m, e|e+1); c2,c3 -> (m+8, e|e+1).
    #pragma unroll
    for (int i = 0; i < 4; i++) {
        #pragma unroll
        for (int j = 0; j < 4; j++) {
            const int m  = m0 + wm + i * 16 + (lane >> 2);
            const int e  = e0 + wn + j * 8 + ((lane & 3) << 1);
            #pragma unroll
            for (int half = 0; half < 2; half++) {
                const int mm = m + half * 8;
                const int bb = mm >> 11;
                const int nn = mm & (N - 1);
                float2 v = make_float2(acc[i][j][2*half + 0] * scale,
                                       acc[i][j][2*half + 1] * scale);
                if (mode != 3) {
                    const int h = e >> 6, dh = e & 63;
                    *(float2*)&C[(((size_t)(bb * H + h)) * N + nn) * DH + dh] = v;
                } else {
                    *(float2*)&C[(size_t)mm * D + e] = v;
                }
            }
        }
    }
}

// ---------------------------------------------------------------------------
// Flash attention, fp32 (unchanged from passing R4 kernel).
// ---------------------------------------------------------------------------
__device__ __forceinline__ int swz64f(int row, int g) {  // g = col/4, 0..15
    return row * 64 + ((g ^ ((row >> 2) & 7)) << 2);
}

__global__ void __launch_bounds__(256) attn_kernel()
{
    __shared__ __align__(16) float Qs [64 * 64];
    __shared__ __align__(16) float KPs[64 * 64];   // K tile, then P tile
    __shared__ __align__(16) float Vs [64 * 64];

    const int tid = threadIdx.x;
    const int bh  = blockIdx.y;
    const int n0  = blockIdx.x * 64;
    const float* Qb = g_q + (size_t)bh * N * DH;
    const float* Kb = g_k + (size_t)bh * N * DH;
    const float* Vb = g_v + (size_t)bh * N * DH;

    const int r0 = (tid >> 4) << 2;
    const int c0 = (tid & 15) << 2;

    #pragma unroll
    for (int t = 0; t < 4; t++) {
        int idx = tid + t * 256;
        int row = idx >> 4;
        int g   = idx & 15;
        *(float4*)&Qs[swz64f(row, g)] =
            *(const float4*)&Qb[(size_t)(n0 + row) * DH + (g << 2)];
    }

    float mI[4], lI[4], o[4][4];
    #pragma unroll
    for (int i = 0; i < 4; i++) {
        mI[i] = -1e30f; lI[i] = 0.f;
        #pragma unroll
        for (int j = 0; j < 4; j++) o[i][j] = 0.f;
    }

    for (int kt = 0; kt < N; kt += 64) {
        __syncthreads();
        #pragma unroll
        for (int t = 0; t < 4; t++) {
            int idx = tid + t * 256;
            int row = idx >> 4;
            int g   = idx & 15;
            *(float4*)&KPs[swz64f(row, g)] =
                *(const float4*)&Kb[(size_t)(kt + row) * DH + (g << 2)];
            *(float4*)&Vs[swz64f(row, g)] =
                *(const float4*)&Vb[(size_t)(kt + row) * DH + (g << 2)];
        }
        __syncthreads();

        float s[4][4];
        #pragma unroll
        for (int i = 0; i < 4; i++)
            #pragma unroll
            for (int j = 0; j < 4; j++) s[i][j] = 0.f;

        #pragma unroll
        for (int kk = 0; kk < 64; kk += 4) {
            const int g = kk >> 2;
            float4 a[4], bq[4];
            #pragma unroll
            for (int i = 0; i < 4; i++) a[i]  = *(const float4*)&Qs[swz64f(r0 + i, g)];
            #pragma unroll
            for (int j = 0; j < 4; j++) bq[j] = *(const float4*)&KPs[swz64f(c0 + j, g)];
            #pragma unroll
            for (int i = 0; i < 4; i++)
                #pragma unroll
                for (int j = 0; j < 4; j++)
                    s[i][j] += a[i].x * bq[j].x + a[i].y * bq[j].y
                             + a[i].z * bq[j].z + a[i].w * bq[j].w;
        }

        #pragma unroll
        for (int i = 0; i < 4; i++) {
            float mx = fmaxf(fmaxf(s[i][0], s[i][1]), fmaxf(s[i][2], s[i][3]));
            mx = fmaxf(mx, __shfl_xor_sync(0xffffffffu, mx, 1));
            mx = fmaxf(mx, __shfl_xor_sync(0xffffffffu, mx, 2));
            mx = fmaxf(mx, __shfl_xor_sync(0xffffffffu, mx, 4));
            mx = fmaxf(mx, __shfl_xor_sync(0xffffffffu, mx, 8));
            const float mnew = fmaxf(mI[i], mx);
            const float corr = __expf(mI[i] - mnew);
            mI[i] = mnew;
            float rs = 0.f;
            #pragma unroll
            for (int j = 0; j < 4; j++) {
                s[i][j] = __expf(s[i][j] - mnew);
                rs += s[i][j];
            }
            rs += __shfl_xor_sync(0xffffffffu, rs, 1);
            rs += __shfl_xor_sync(0xffffffffu, rs, 2);
            rs += __shfl_xor_sync(0xffffffffu, rs, 4);
            rs += __shfl_xor_sync(0xffffffffu, rs, 8);
            lI[i] = lI[i] * corr + rs;
            #pragma unroll
            for (int j = 0; j < 4; j++) o[i][j] *= corr;
        }

        __syncthreads();
        #pragma unroll
        for (int i = 0; i < 4; i++)
            *(float4*)&KPs[swz64f(r0 + i, c0 >> 2)] =
                make_float4(s[i][0], s[i][1], s[i][2], s[i][3]);
        __syncthreads();

        #pragma unroll
        for (int c = 0; c < 64; c += 4) {
            float4 p[4], vv[4];
            #pragma unroll
            for (int i = 0; i < 4; i++) p[i]  = *(const float4*)&KPs[swz64f(r0 + i, c >> 2)];
            #pragma unroll
            for (int t = 0; t < 4; t++) vv[t] = *(const float4*)&Vs[swz64f(c + t, c0 >> 2)];
            #pragma unroll
            for (int i = 0; i < 4; i++) {
                o[i][0] += p[i].x * vv[0].x + p[i].y * vv[1].x + p[i].z * vv[2].x + p[i].w * vv[3].x;
                o[i][1] += p[i].x * vv[0].y + p[i].y * vv[1].y + p[i].z * vv[2].y + p[i].w * vv[3].y;
                o[i][2] += p[i].x * vv[0].z + p[i].y * vv[1].z + p[i].z * vv[2].z + p[i].w * vv[3].z;
                o[i][3] += p[i].x * vv[0].w + p[i].y * vv[1].w + p[i].z * vv[2].w + p[i].w * vv[3].w;
            }
        }
    }

    const int bb = bh / H, hh = bh % H;
    #pragma unroll
    for (int i = 0; i < 4; i++) {
        const float inv = 1.f / lI[i];
        const int n = n0 + r0 + i;
        float4 v = make_float4(o[i][0] * inv, o[i][1] * inv,
                               o[i][2] * inv, o[i][3] * inv);
        *(float4*)&g_attn[((size_t)(bb * N + n)) * D + hh * DH + c0] = v;
    }
}

// ---------------------------------------------------------------------------
// kernel_launch. Inputs by element count: x = M*D; weights = D*D in order
// (Wq, Wk, Wv, Wo); mask ignored. Launches only; no driver/attribute APIs.
// ---------------------------------------------------------------------------
extern "C" void kernel_launch(void* const* d_in, const int* in_sizes, int n_in,
                              void* d_out, int out_size) {
    (void)out_size;
    const float* x = nullptr;
    const float* Wt[4] = {nullptr, nullptr, nullptr, nullptr};
    int c = 0;
    for (int i = 0; i < n_in; i++) {
        if (in_sizes[i] == M * D && !x) x = (const float*)d_in[i];
        else if (in_sizes[i] == D * D && c < 4) Wt[c++] = (const float*)d_in[i];
    }
    float* out = (float*)d_out;

    dim3 gg(M / 128, D / 128);   // (64, 8)
    gemm_mma<<<gg, 256>>>(x, Wt[0], nullptr, 0.125f, 0);  // Q (1/sqrt(DH) folded)
    gemm_mma<<<gg, 256>>>(x, Wt[1], nullptr, 1.0f,   1);  // K
    gemm_mma<<<gg, 256>>>(x, Wt[2], nullptr, 1.0f,   2);  // V

    attn_kernel<<<dim3(N / 64, B * H), 256>>>();

    gemm_mma<<<gg, 256>>>(nullptr, Wt[3], out, 1.0f, 3);  // Wo
}

// round 7
// speedup vs baseline: 2.5835x; 1.7908x over previous
#include <cuda_runtime.h>
#include <cuda_bf16.h>
#include <cstdint>

// Problem constants
constexpr int B  = 4;
constexpr int N  = 2048;
constexpr int D  = 1024;
constexpr int H  = 16;
constexpr int DH = 64;
constexpr int M  = B * N;   // 8192

// Scratch (device globals; referenced directly from device code).
// Q/K/V kept as pre-split bf16 hi/lo pairs in [b,h,n,dh] layout.
__device__ __nv_bfloat16 g_qh[M * D], g_ql[M * D];
__device__ __nv_bfloat16 g_kh[M * D], g_kl[M * D];
__device__ __nv_bfloat16 g_vh[M * D], g_vl[M * D];
__device__ float g_attn[M * D];     // [b,n,d] merged heads (fp32)

__device__ __forceinline__ uint32_t smem_u32(const void* p) {
    uint32_t a;
    asm("{ .reg .u64 t; cvta.to.shared.u64 t, %1; cvt.u32.u64 %0, t; }"
        : "=r"(a) : "l"(p));
    return a;
}
__device__ __forceinline__ uint32_t swz128(uint32_t off) {
    return off ^ ((off >> 3) & 0x70);
}

#define LDSM4(r0, r1, r2, r3, a)                                            \
    asm volatile("ldmatrix.sync.aligned.m8n8.x4.shared.b16 "                \
                 "{%0,%1,%2,%3}, [%4];"                                     \
                 : "=r"(r0), "=r"(r1), "=r"(r2), "=r"(r3) : "r"(a))

#define LDSM4T(r0, r1, r2, r3, a)                                           \
    asm volatile("ldmatrix.sync.aligned.m8n8.x4.trans.shared.b16 "          \
                 "{%0,%1,%2,%3}, [%4];"                                     \
                 : "=r"(r0), "=r"(r1), "=r"(r2), "=r"(r3) : "r"(a))

#define MMA16816(c, a, b)                                                   \
    asm volatile("mma.sync.aligned.m16n8k16.row.col.f32.bf16.bf16.f32 "     \
                 "{%0,%1,%2,%3}, {%4,%5,%6,%7}, {%8,%9}, {%0,%1,%2,%3};"    \
                 : "+f"((c)[0]), "+f"((c)[1]), "+f"((c)[2]), "+f"((c)[3])   \
                 : "r"((a)[0]), "r"((a)[1]), "r"((a)[2]), "r"((a)[3]),      \
                   "r"((b)[0]), "r"((b)[1]))

// Split 8 fp32 into packed bf16 hi / lo pairs (2-term compensation).
__device__ __forceinline__ void split8(const float4 u, const float4 v,
                                       uint32_t* hi, uint32_t* lo)
{
    float f[8] = { u.x, u.y, u.z, u.w, v.x, v.y, v.z, v.w };
    #pragma unroll
    for (int p = 0; p < 4; p++) {
        __nv_bfloat162 h = __floats2bfloat162_rn(f[2*p], f[2*p+1]);
        float2 hf = __bfloat1622float2(h);
        __nv_bfloat162 l = __floats2bfloat162_rn(f[2*p]   - hf.x,
                                                 f[2*p+1] - hf.y);
        hi[p] = *(uint32_t*)&h;
        lo[p] = *(uint32_t*)&l;
    }
}

// ---------------------------------------------------------------------------
// Tensor-core GEMM (NT) via mma.sync bf16 + 2-term split compensation.
// C[m,e] = scale * sum_d A[m,d] * W[e,d] ; D = Ah*Bh + Ah*Bl + Al*Bh (fp32 acc)
// CTA 128x128, BK=32, 256 threads = 8 warps (2M x 4N), warp tile 64x32.
// mode 0/1/2: A = x, output = split bf16 hi/lo Q/K/V arrays ([b,h,n,dh]).
// mode 3:     A = g_attn, output = Cout fp32 [m,e].
// ---------------------------------------------------------------------------
__global__ void __launch_bounds__(256) gemm_mma(
    const float* __restrict__ A_in, const float* __restrict__ W,
    float* __restrict__ Cout, float scale, int mode)
{
    __shared__ __align__(128) char smA[128 * 128];   // 16KB
    __shared__ __align__(128) char smB[128 * 128];   // 16KB

    const float* A = (mode == 3) ? (const float*)g_attn : A_in;
    __nv_bfloat16 *Ch = nullptr, *Cl = nullptr;
    if      (mode == 0) { Ch = g_qh; Cl = g_ql; }
    else if (mode == 1) { Ch = g_kh; Cl = g_kl; }
    else if (mode == 2) { Ch = g_vh; Cl = g_vl; }

    const int tid   = threadIdx.x;
    const int lane  = tid & 31;
    const int wid   = tid >> 5;
    const int wm    = (wid >> 2) * 64;
    const int wn    = (wid & 3) * 32;
    const int m0    = blockIdx.x * 128;
    const int e0    = blockIdx.y * 128;

    const uint32_t uA = smem_u32(smA);
    const uint32_t uB = smem_u32(smB);

    const int lrow  = tid >> 1;
    const int lhalf = tid & 1;

    float acc[4][4][4];
    #pragma unroll
    for (int i = 0; i < 4; i++)
        #pragma unroll
        for (int j = 0; j < 4; j++)
            #pragma unroll
            for (int f = 0; f < 4; f++) acc[i][j][f] = 0.f;

    const int q  = lane >> 3;
    const int r8 = lane & 7;
    const int a_row_in = (q & 1) * 8 + r8;
    const int a_kb     = (q >> 1) * 16;
    const int b_tile_in = (q >> 1);
    const int b_kb      = (q & 1) * 16;

    for (int kc = 0; kc < D / 32; kc++) {
        const int k0 = kc * 32;

        float4 ra[4], rb[4];
        const float4* arow = (const float4*)&A[(size_t)(m0 + lrow) * D + k0] + lhalf * 4;
        const float4* brow = (const float4*)&W[(size_t)(e0 + lrow) * D + k0] + lhalf * 4;
        #pragma unroll
        for (int g4 = 0; g4 < 4; g4++) { ra[g4] = arow[g4]; rb[g4] = brow[g4]; }

        __syncthreads();

        {
            uint32_t hi[8], lo[8];
            split8(ra[0], ra[1], hi,     lo);
            split8(ra[2], ra[3], hi + 4, lo + 4);
            const uint32_t rbyte = lrow * 128 + lhalf * 32;
            *(uint4*)(smA + swz128(rbyte))           = *(uint4*)(hi);
            *(uint4*)(smA + swz128(rbyte + 16))      = *(uint4*)(hi + 4);
            *(uint4*)(smA + swz128(rbyte + 64))      = *(uint4*)(lo);
            *(uint4*)(smA + swz128(rbyte + 64 + 16)) = *(uint4*)(lo + 4);

            split8(rb[0], rb[1], hi,     lo);
            split8(rb[2], rb[3], hi + 4, lo + 4);
            *(uint4*)(smB + swz128(rbyte))           = *(uint4*)(hi);
            *(uint4*)(smB + swz128(rbyte + 16))      = *(uint4*)(hi + 4);
            *(uint4*)(smB + swz128(rbyte + 64))      = *(uint4*)(lo);
            *(uint4*)(smB + swz128(rbyte + 64 + 16)) = *(uint4*)(lo + 4);
        }
        __syncthreads();

        #pragma unroll
        for (int s = 0; s < 2; s++) {
            uint32_t ah[4][4], al[4][4], bh[4][2], bl[4][2];

            #pragma unroll
            for (int i = 0; i < 4; i++) {
                const uint32_t rowb = (wm + i * 16 + a_row_in) * 128 + s * 32 + a_kb;
                LDSM4(ah[i][0], ah[i][1], ah[i][2], ah[i][3], uA + swz128(rowb));
                LDSM4(al[i][0], al[i][1], al[i][2], al[i][3], uA + swz128(rowb + 64));
            }
            #pragma unroll
            for (int jp = 0; jp < 2; jp++) {
                const uint32_t rowb =
                    (wn + (jp * 2 + b_tile_in) * 8 + r8) * 128 + s * 32 + b_kb;
                LDSM4(bh[2*jp][0], bh[2*jp][1], bh[2*jp+1][0], bh[2*jp+1][1],
                      uB + swz128(rowb));
                LDSM4(bl[2*jp][0], bl[2*jp][1], bl[2*jp+1][0], bl[2*jp+1][1],
                      uB + swz128(rowb + 64));
            }

            #pragma unroll
            for (int i = 0; i < 4; i++)
                #pragma unroll
                for (int j = 0; j < 4; j++) {
                    MMA16816(acc[i][j], ah[i], bh[j]);
                    MMA16816(acc[i][j], ah[i], bl[j]);
                    MMA16816(acc[i][j], al[i], bh[j]);
                }
        }
    }

    // Epilogue.
    #pragma unroll
    for (int i = 0; i < 4; i++) {
        #pragma unroll
        for (int j = 0; j < 4; j++) {
            const int m  = m0 + wm + i * 16 + (lane >> 2);
            const int e  = e0 + wn + j * 8 + ((lane & 3) << 1);
            #pragma unroll
            for (int half = 0; half < 2; half++) {
                const int mm = m + half * 8;
                const int bb = mm >> 11;
                const int nn = mm & (N - 1);
                float vx = acc[i][j][2*half + 0] * scale;
                float vy = acc[i][j][2*half + 1] * scale;
                if (mode != 3) {
                    const int h = e >> 6, dh = e & 63;
                    const size_t idx = (((size_t)(bb * H + h)) * N + nn) * DH + dh;
                    __nv_bfloat162 hv = __floats2bfloat162_rn(vx, vy);
                    float2 hf = __bfloat1622float2(hv);
                    __nv_bfloat162 lv = __floats2bfloat162_rn(vx - hf.x, vy - hf.y);
                    *(uint32_t*)&Ch[idx] = *(uint32_t*)&hv;
                    *(uint32_t*)&Cl[idx] = *(uint32_t*)&lv;
                } else {
                    *(float2*)&Cout[(size_t)mm * D + e] = make_float2(vx, vy);
                }
            }
        }
    }
}

// ---------------------------------------------------------------------------
// Flash attention on mma.sync bf16 with split compensation.
// CTA: 128 query rows (8 warps x 16 rows), key tiles of 64, full 64-dh output.
// S = Qh*Kh + Qh*Kl + Ql*Kh ; P split into hi/lo ; O += Ph*Vh + Ph*Vl + Pl*Vh.
// P fragments come directly from S accumulator registers (C->A layout match).
// SMEM 32KB static: Q staging (hi 0..16K, lo 16..32K) reused as Kh/Kl/Vh/Vl.
// ---------------------------------------------------------------------------
__global__ void __launch_bounds__(256) attn_mma()
{
    __shared__ __align__(128) char sm[32768];
    const uint32_t uS = smem_u32(sm);
    constexpr uint32_t oKh = 0, oKl = 8192, oVh = 16384, oVl = 24576;

    const int tid  = threadIdx.x;
    const int lane = tid & 31;
    const int wid  = tid >> 5;
    const int bh   = blockIdx.y;              // b*H + h
    const int n0   = blockIdx.x * 128;
    const int wq   = wid * 16;                // warp's query-row base in tile

    const int q  = lane >> 3;
    const int r8 = lane & 7;
    const int a_row = (q & 1) * 8 + r8;
    const int a_kb  = (q >> 1) * 16;
    const int b_ti  = (q >> 1);
    const int b_kb  = (q & 1) * 16;

    const size_t bhbase = (size_t)bh * N * DH;

    // ---- Stage Q (hi at 0, lo at +16KB), extract A fragments, keep in regs.
    #pragma unroll
    for (int t = 0; t < 4; t++) {
        int idx = tid + t * 256;        // 0..1023
        int row = idx >> 3;             // 0..127
        int g16 = idx & 7;
        const size_t src = bhbase + (size_t)(n0 + row) * DH;
        *(uint4*)(sm + swz128(row * 128 + g16 * 16)) =
            *((const uint4*)&g_qh[src] + g16);
        *(uint4*)(sm + 16384 + swz128(row * 128 + g16 * 16)) =
            *((const uint4*)&g_ql[src] + g16);
    }
    __syncthreads();

    uint32_t qh[4][4], ql[4][4];
    #pragma unroll
    for (int s = 0; s < 4; s++) {
        const uint32_t rowb = (wq + a_row) * 128 + s * 32 + a_kb;
        LDSM4(qh[s][0], qh[s][1], qh[s][2], qh[s][3], uS + swz128(rowb));
        LDSM4(ql[s][0], ql[s][1], ql[s][2], ql[s][3], uS + 16384 + swz128(rowb));
    }

    float m0 = -1e30f, m1 = -1e30f, l0 = 0.f, l1 = 0.f;
    float o[8][4];
    #pragma unroll
    for (int j = 0; j < 8; j++)
        #pragma unroll
        for (int f = 0; f < 4; f++) o[j][f] = 0.f;

    for (int kt = 0; kt < N; kt += 64) {
        __syncthreads();   // all warps done with previous tile (and Q staging)
        // Load Kh/Kl/Vh/Vl tiles: 4 arrays x 64 rows x 8 x 16B = 8 uint4/thread
        #pragma unroll
        for (int t = 0; t < 8; t++) {
            int idx = tid + t * 256;    // 0..2047
            int arr = idx >> 9;
            int rem = idx & 511;
            int row = rem >> 3, g16 = rem & 7;
            const __nv_bfloat16* gsrc =
                (arr == 0) ? g_kh : (arr == 1) ? g_kl : (arr == 2) ? g_vh : g_vl;
            uint4 val = *((const uint4*)&gsrc[bhbase + (size_t)(kt + row) * DH] + g16);
            *(uint4*)(sm + arr * 8192 + swz128(row * 128 + g16 * 16)) = val;
        }
        __syncthreads();

        // ---- S = Q @ K^T  (16 x 64 per warp)
        float sacc[8][4];
        #pragma unroll
        for (int j = 0; j < 8; j++)
            #pragma unroll
            for (int f = 0; f < 4; f++) sacc[j][f] = 0.f;

        #pragma unroll
        for (int s = 0; s < 4; s++) {
            uint32_t kh[8][2], kl[8][2];
            #pragma unroll
            for (int jp = 0; jp < 4; jp++) {
                const uint32_t rowb = (jp * 16 + b_ti * 8 + r8) * 128 + s * 32 + b_kb;
                LDSM4(kh[2*jp][0], kh[2*jp][1], kh[2*jp+1][0], kh[2*jp+1][1],
                      uS + oKh + swz128(rowb));
                LDSM4(kl[2*jp][0], kl[2*jp][1], kl[2*jp+1][0], kl[2*jp+1][1],
                      uS + oKl + swz128(rowb));
            }
            #pragma unroll
            for (int j = 0; j < 8; j++) {
                MMA16816(sacc[j], qh[s], kh[j]);
                MMA16816(sacc[j], qh[s], kl[j]);
                MMA16816(sacc[j], ql[s], kh[j]);
            }
        }

        // ---- Online softmax (rows r = lane>>2 and r+8; quad reduction)
        float mx0 = -1e30f, mx1 = -1e30f;
        #pragma unroll
        for (int j = 0; j < 8; j++) {
            mx0 = fmaxf(mx0, fmaxf(sacc[j][0], sacc[j][1]));
            mx1 = fmaxf(mx1, fmaxf(sacc[j][2], sacc[j][3]));
        }
        mx0 = fmaxf(mx0, __shfl_xor_sync(0xffffffffu, mx0, 1));
        mx0 = fmaxf(mx0, __shfl_xor_sync(0xffffffffu, mx0, 2));
        mx1 = fmaxf(mx1, __shfl_xor_sync(0xffffffffu, mx1, 1));
        mx1 = fmaxf(mx1, __shfl_xor_sync(0xffffffffu, mx1, 2));
        const float mn0 = fmaxf(m0, mx0), mn1 = fmaxf(m1, mx1);
        const float c0 = __expf(m0 - mn0), c1 = __expf(m1 - mn1);
        m0 = mn0; m1 = mn1;

        float rs0 = 0.f, rs1 = 0.f;
        uint32_t ph[8][2], pl[8][2];
        #pragma unroll
        for (int j = 0; j < 8; j++) {
            float p00 = __expf(sacc[j][0] - mn0);
            float p01 = __expf(sacc[j][1] - mn0);
            float p10 = __expf(sacc[j][2] - mn1);
            float p11 = __expf(sacc[j][3] - mn1);
            rs0 += p00 + p01; rs1 += p10 + p11;
            __nv_bfloat162 h0 = __floats2bfloat162_rn(p00, p01);
            float2 hf0 = __bfloat1622float2(h0);
            __nv_bfloat162 l0v = __floats2bfloat162_rn(p00 - hf0.x, p01 - hf0.y);
            ph[j][0] = *(uint32_t*)&h0; pl[j][0] = *(uint32_t*)&l0v;
            __nv_bfloat162 h1 = __floats2bfloat162_rn(p10, p11);
            float2 hf1 = __bfloat1622float2(h1);
            __nv_bfloat162 l1v = __floats2bfloat162_rn(p10 - hf1.x, p11 - hf1.y);
            ph[j][1] = *(uint32_t*)&h1; pl[j][1] = *(uint32_t*)&l1v;
        }
        rs0 += __shfl_xor_sync(0xffffffffu, rs0, 1);
        rs0 += __shfl_xor_sync(0xffffffffu, rs0, 2);
        rs1 += __shfl_xor_sync(0xffffffffu, rs1, 1);
        rs1 += __shfl_xor_sync(0xffffffffu, rs1, 2);
        l0 = l0 * c0 + rs0;
        l1 = l1 * c1 + rs1;

        #pragma unroll
        for (int j = 0; j < 8; j++) {
            o[j][0] *= c0; o[j][1] *= c0; o[j][2] *= c1; o[j][3] *= c1;
        }

        // ---- O += P @ V   (keys as k-dim; V via ldmatrix.trans as B operand)
        #pragma unroll
        for (int s = 0; s < 4; s++) {
            uint32_t ah[4] = { ph[2*s][0], ph[2*s][1], ph[2*s+1][0], ph[2*s+1][1] };
            uint32_t al[4] = { pl[2*s][0], pl[2*s][1], pl[2*s+1][0], pl[2*s+1][1] };
            uint32_t vh[8][2], vl[8][2];
            #pragma unroll
            for (int jp = 0; jp < 4; jp++) {
                const int vrow  = s * 16 + (q & 1) * 8 + r8;
                const int vcolb = jp * 32 + (q >> 1) * 16;
                const uint32_t rowb = vrow * 128 + vcolb;
                LDSM4T(vh[2*jp][0], vh[2*jp][1], vh[2*jp+1][0], vh[2*jp+1][1],
                       uS + oVh + swz128(rowb));
                LDSM4T(vl[2*jp][0], vl[2*jp][1], vl[2*jp+1][0], vl[2*jp+1][1],
                       uS + oVl + swz128(rowb));
            }
            #pragma unroll
            for (int j = 0; j < 8; j++) {
                MMA16816(o[j], ah, vh[j]);
                MMA16816(o[j], ah, vl[j]);
                MMA16816(o[j], al, vh[j]);
            }
        }
    }

    // ---- Epilogue: O / l, write merged-heads fp32 [b, n, h*DH + dh]
    const int bb = bh / H, hh = bh % H;
    const float i0 = 1.f / l0, i1 = 1.f / l1;
    const int nr = n0 + wq + (lane >> 2);
    #pragma unroll
    for (int j = 0; j < 8; j++) {
        const int dh = j * 8 + ((lane & 3) << 1);
        *(float2*)&g_attn[((size_t)(bb * N + nr)) * D + hh * DH + dh] =
            make_float2(o[j][0] * i0, o[j][1] * i0);
        *(float2*)&g_attn[((size_t)(bb * N + nr + 8)) * D + hh * DH + dh] =
            make_float2(o[j][2] * i1, o[j][3] * i1);
    }
}

// ---------------------------------------------------------------------------
// kernel_launch. Inputs by element count: x = M*D; weights = D*D in order
// (Wq, Wk, Wv, Wo); mask ignored. Launches only; no driver/attribute APIs.
// ---------------------------------------------------------------------------
extern "C" void kernel_launch(void* const* d_in, const int* in_sizes, int n_in,
                              void* d_out, int out_size) {
    (void)out_size;
    const float* x = nullptr;
    const float* Wt[4] = {nullptr, nullptr, nullptr, nullptr};
    int c = 0;
    for (int i = 0; i < n_in; i++) {
        if (in_sizes[i] == M * D && !x) x = (const float*)d_in[i];
        else if (in_sizes[i] == D * D && c < 4) Wt[c++] = (const float*)d_in[i];
    }
    float* out = (float*)d_out;

    dim3 gg(M / 128, D / 128);   // (64, 8)
    gemm_mma<<<gg, 256>>>(x, Wt[0], nullptr, 0.125f, 0);  // Q (1/sqrt(DH) folded)
    gemm_mma<<<gg, 256>>>(x, Wt[1], nullptr, 1.0f,   1);  // K
    gemm_mma<<<gg, 256>>>(x, Wt[2], nullptr, 1.0f,   2);  // V

    attn_mma<<<dim3(N / 128, B * H), 256>>>();

    gemm_mma<<<gg, 256>>>(nullptr, Wt[3], out, 1.0f, 3);  // Wo
}

// round 8
// speedup vs baseline: 3.7069x; 1.4348x over previous
#include <cuda_runtime.h>
#include <cuda_bf16.h>
#include <cstdint>

// Problem constants
constexpr int B  = 4;
constexpr int N  = 2048;
constexpr int D  = 1024;
constexpr int H  = 16;
constexpr int DH = 64;
constexpr int M  = B * N;   // 8192

// Scratch (device globals; referenced directly from device code).
__device__ __align__(16) __nv_bfloat16 g_xh[M * D], g_xl[M * D];     // split x
__device__ __align__(16) __nv_bfloat16 g_wh[4 * D * D], g_wl[4 * D * D]; // split weights
__device__ __align__(16) __nv_bfloat16 g_qh[M * D], g_ql[M * D];     // [b,h,n,dh]
__device__ __align__(16) __nv_bfloat16 g_kh[M * D], g_kl[M * D];
__device__ __align__(16) __nv_bfloat16 g_vh[M * D], g_vl[M * D];
__device__ __align__(16) __nv_bfloat16 g_aoh[M * D], g_aol[M * D];   // attn out split [b,n,d]

__device__ __forceinline__ uint32_t smem_u32(const void* p) {
    uint32_t a;
    asm("{ .reg .u64 t; cvta.to.shared.u64 t, %1; cvt.u32.u64 %0, t; }"
        : "=r"(a) : "l"(p));
    return a;
}
__device__ __forceinline__ uint32_t swz128(uint32_t off) {
    return off ^ ((off >> 3) & 0x70);
}

#define LDSM4(r0, r1, r2, r3, a)                                            \
    asm volatile("ldmatrix.sync.aligned.m8n8.x4.shared.b16 "                \
                 "{%0,%1,%2,%3}, [%4];"                                     \
                 : "=r"(r0), "=r"(r1), "=r"(r2), "=r"(r3) : "r"(a))

#define LDSM4T(r0, r1, r2, r3, a)                                           \
    asm volatile("ldmatrix.sync.aligned.m8n8.x4.trans.shared.b16 "          \
                 "{%0,%1,%2,%3}, [%4];"                                     \
                 : "=r"(r0), "=r"(r1), "=r"(r2), "=r"(r3) : "r"(a))

#define MMA16816(c, a, b)                                                   \
    asm volatile("mma.sync.aligned.m16n8k16.row.col.f32.bf16.bf16.f32 "     \
                 "{%0,%1,%2,%3}, {%4,%5,%6,%7}, {%8,%9}, {%0,%1,%2,%3};"    \
                 : "+f"((c)[0]), "+f"((c)[1]), "+f"((c)[2]), "+f"((c)[3])   \
                 : "r"((a)[0]), "r"((a)[1]), "r"((a)[2]), "r"((a)[3]),      \
                   "r"((b)[0]), "r"((b)[1]))

#define CP16(dst, src)                                                      \
    asm volatile("cp.async.cg.shared.global [%0], [%1], 16;"                \
                 :: "r"(dst), "l"(src))
#define CP_COMMIT() asm volatile("cp.async.commit_group;")
#define CP_WAIT(n)  asm volatile("cp.async.wait_group %0;" :: "n"(n))

// Split packed: two fp32 -> bf16x2 hi + bf16x2 lo
__device__ __forceinline__ void split2(float x, float y, uint32_t& h, uint32_t& l) {
    __nv_bfloat162 hv = __floats2bfloat162_rn(x, y);
    float2 hf = __bfloat1622float2(hv);
    __nv_bfloat162 lv = __floats2bfloat162_rn(x - hf.x, y - hf.y);
    h = *(uint32_t*)&hv; l = *(uint32_t*)&lv;
}

// ---------------------------------------------------------------------------
// Elementwise pre-split: x -> g_xh/g_xl ; W0..W3 -> g_wh/g_wl.
// One thread = 4 floats. Total = M*D + 4*D*D = 12582912 floats.
// ---------------------------------------------------------------------------
constexpr int SPLIT_TOTAL = M * D + 4 * D * D;

__global__ void __launch_bounds__(256) split_all(
    const float* __restrict__ x,
    const float* __restrict__ w0, const float* __restrict__ w1,
    const float* __restrict__ w2, const float* __restrict__ w3)
{
    const size_t i = ((size_t)blockIdx.x * 256 + threadIdx.x) * 4;
    const float* src;
    __nv_bfloat16 *dh, *dl;
    size_t off;
    if (i < (size_t)M * D) {
        src = x; dh = g_xh; dl = g_xl; off = i;
    } else {
        size_t r = i - (size_t)M * D;
        int wi = (int)(r / (D * D));
        off = r % (D * D);
        src = (wi == 0) ? w0 : (wi == 1) ? w1 : (wi == 2) ? w2 : w3;
        dh = g_wh + (size_t)wi * D * D;
        dl = g_wl + (size_t)wi * D * D;
    }
    float4 v = *(const float4*)(src + off);
    uint32_t h0, l0, h1, l1;
    split2(v.x, v.y, h0, l0);
    split2(v.z, v.w, h1, l1);
    *(uint2*)(dh + off) = make_uint2(h0, h1);
    *(uint2*)(dl + off) = make_uint2(l0, l1);
}

// ---------------------------------------------------------------------------
// bf16 GEMM (NT) with pre-split inputs and cp.async double buffering.
// C[m,e] = scale * (Ah*Bh + Ah*Bl + Al*Bh)[m,e]  (fp32 accum)
// CTA tile 128(M) x 64(N), BK=32, 2 stages, 48KB static SMEM.
// 256 threads = 8 warps (4M x 2N), warp tile 32x32.
// SMEM stage: A at +0 (128 rows x [hi 64B | lo 64B]), B at +16384 (64 rows).
// mode 0/1/2: A = x splits, out = q/k/v splits ([b,h,n,dh], scale folded).
// mode 3:     A = attn-out splits, out = Cout fp32 [m,e]. Weight = g_w*[mode].
// ---------------------------------------------------------------------------
constexpr int STG = 24576;   // bytes per stage

__device__ __forceinline__ void gemm_load_stage(
    uint32_t smbase, int tid, int m0, int e0, int k0,
    const __nv_bfloat16* Ah, const __nv_bfloat16* Al,
    const __nv_bfloat16* Bh, const __nv_bfloat16* Bl)
{
    // A: 1024 x 16B units (hi 512, lo 512)
    #pragma unroll
    for (int t = 0; t < 4; t++) {
        int idx = tid + t * 256;
        int arr = idx >> 9;
        int rem = idx & 511;
        int row = rem >> 2, u = rem & 3;
        const __nv_bfloat16* s = (arr ? Al : Ah) + (size_t)(m0 + row) * D + k0 + u * 8;
        CP16(smbase + swz128(row * 128 + arr * 64 + u * 16), s);
    }
    // B: 512 x 16B units
    #pragma unroll
    for (int t = 0; t < 2; t++) {
        int idx = tid + t * 256;
        int arr = idx >> 8;
        int rem = idx & 255;
        int row = rem >> 2, u = rem & 3;
        const __nv_bfloat16* s = (arr ? Bl : Bh) + (size_t)(e0 + row) * D + k0 + u * 8;
        CP16(smbase + 16384 + swz128(row * 128 + arr * 64 + u * 16), s);
    }
}

__global__ void __launch_bounds__(256) gemm_bf16(
    float* __restrict__ Cout, float scale, int mode)
{
    __shared__ __align__(128) char sm[2 * STG];   // 48KB

    const __nv_bfloat16 *Ah, *Al;
    if (mode < 3) { Ah = g_xh; Al = g_xl; }
    else          { Ah = g_aoh; Al = g_aol; }
    const __nv_bfloat16* Bh = g_wh + (size_t)mode * D * D;
    const __nv_bfloat16* Bl = g_wl + (size_t)mode * D * D;
    __nv_bfloat16 *Ch = nullptr, *Cl = nullptr;
    if      (mode == 0) { Ch = g_qh; Cl = g_ql; }
    else if (mode == 1) { Ch = g_kh; Cl = g_kl; }
    else if (mode == 2) { Ch = g_vh; Cl = g_vl; }

    const int tid  = threadIdx.x;
    const int lane = tid & 31;
    const int wid  = tid >> 5;
    const int wm   = (wid >> 1) * 32;    // 0/32/64/96
    const int wn   = (wid & 1) * 32;     // 0/32
    const int m0   = blockIdx.x * 128;
    const int e0   = blockIdx.y * 64;

    const uint32_t uS = smem_u32(sm);

    const int q  = lane >> 3;
    const int r8 = lane & 7;
    const int a_row = (q & 1) * 8 + r8;
    const int a_kb  = (q >> 1) * 16;
    const int b_ti  = (q >> 1);
    const int b_kb  = (q & 1) * 16;

    float acc[2][4][4];
    #pragma unroll
    for (int i = 0; i < 2; i++)
        #pragma unroll
        for (int j = 0; j < 4; j++)
            #pragma unroll
            for (int f = 0; f < 4; f++) acc[i][j][f] = 0.f;

    constexpr int NC = D / 32;   // 32

    gemm_load_stage(uS, tid, m0, e0, 0, Ah, Al, Bh, Bl);
    CP_COMMIT();

    for (int kc = 0; kc < NC; kc++) {
        if (kc + 1 < NC) {
            gemm_load_stage(uS + ((kc + 1) & 1) * STG, tid, m0, e0, (kc + 1) * 32,
                            Ah, Al, Bh, Bl);
            CP_COMMIT();
            CP_WAIT(1);
        } else {
            CP_WAIT(0);
        }
        __syncthreads();

        const uint32_t uA = uS + (kc & 1) * STG;
        const uint32_t uB = uA + 16384;

        #pragma unroll
        for (int s = 0; s < 2; s++) {
            uint32_t ah[2][4], al[2][4], bh[4][2], bl[4][2];
            #pragma unroll
            for (int i = 0; i < 2; i++) {
                const uint32_t rowb = (wm + i * 16 + a_row) * 128 + s * 32 + a_kb;
                LDSM4(ah[i][0], ah[i][1], ah[i][2], ah[i][3], uA + swz128(rowb));
                LDSM4(al[i][0], al[i][1], al[i][2], al[i][3], uA + swz128(rowb + 64));
            }
            #pragma unroll
            for (int jp = 0; jp < 2; jp++) {
                const uint32_t rowb =
                    (wn + (jp * 2 + b_ti) * 8 + r8) * 128 + s * 32 + b_kb;
                LDSM4(bh[2*jp][0], bh[2*jp][1], bh[2*jp+1][0], bh[2*jp+1][1],
                      uB + swz128(rowb));
                LDSM4(bl[2*jp][0], bl[2*jp][1], bl[2*jp+1][0], bl[2*jp+1][1],
                      uB + swz128(rowb + 64));
            }
            #pragma unroll
            for (int i = 0; i < 2; i++)
                #pragma unroll
                for (int j = 0; j < 4; j++) {
                    MMA16816(acc[i][j], ah[i], bh[j]);
                    MMA16816(acc[i][j], ah[i], bl[j]);
                    MMA16816(acc[i][j], al[i], bh[j]);
                }
        }
        __syncthreads();
    }

    // Epilogue
    #pragma unroll
    for (int i = 0; i < 2; i++) {
        #pragma unroll
        for (int j = 0; j < 4; j++) {
            const int m = m0 + wm + i * 16 + (lane >> 2);
            const int e = e0 + wn + j * 8 + ((lane & 3) << 1);
            #pragma unroll
            for (int half = 0; half < 2; half++) {
                const int mm = m + half * 8;
                const int bb = mm >> 11;
                const int nn = mm & (N - 1);
                float vx = acc[i][j][2*half + 0] * scale;
                float vy = acc[i][j][2*half + 1] * scale;
                if (mode != 3) {
                    const int h = e >> 6, dh = e & 63;
                    const size_t idx = (((size_t)(bb * H + h)) * N + nn) * DH + dh;
                    uint32_t hv, lv;
                    split2(vx, vy, hv, lv);
                    *(uint32_t*)&Ch[idx] = hv;
                    *(uint32_t*)&Cl[idx] = lv;
                } else {
                    *(float2*)&Cout[(size_t)mm * D + e] = make_float2(vx, vy);
                }
            }
        }
    }
}

// ---------------------------------------------------------------------------
// Flash attention on mma.sync bf16 with split compensation (from passing R7).
// Epilogue now writes split bf16 to g_aoh/g_aol (merged heads [b,n,d]).
// ---------------------------------------------------------------------------
__global__ void __launch_bounds__(256) attn_mma()
{
    __shared__ __align__(128) char sm[32768];
    const uint32_t uS = smem_u32(sm);
    constexpr uint32_t oKh = 0, oKl = 8192, oVh = 16384, oVl = 24576;

    const int tid  = threadIdx.x;
    const int lane = tid & 31;
    const int wid  = tid >> 5;
    const int bh   = blockIdx.y;
    const int n0   = blockIdx.x * 128;
    const int wq   = wid * 16;

    const int q  = lane >> 3;
    const int r8 = lane & 7;
    const int a_row = (q & 1) * 8 + r8;
    const int a_kb  = (q >> 1) * 16;
    const int b_ti  = (q >> 1);
    const int b_kb  = (q & 1) * 16;

    const size_t bhbase = (size_t)bh * N * DH;

    // Stage Q (hi at 0, lo at +16KB), extract fragments, keep in regs.
    #pragma unroll
    for (int t = 0; t < 4; t++) {
        int idx = tid + t * 256;
        int row = idx >> 3;
        int g16 = idx & 7;
        const size_t src = bhbase + (size_t)(n0 + row) * DH;
        *(uint4*)(sm + swz128(row * 128 + g16 * 16)) =
            *((const uint4*)&g_qh[src] + g16);
        *(uint4*)(sm + 16384 + swz128(row * 128 + g16 * 16)) =
            *((const uint4*)&g_ql[src] + g16);
    }
    __syncthreads();

    uint32_t qh[4][4], ql[4][4];
    #pragma unroll
    for (int s = 0; s < 4; s++) {
        const uint32_t rowb = (wq + a_row) * 128 + s * 32 + a_kb;
        LDSM4(qh[s][0], qh[s][1], qh[s][2], qh[s][3], uS + swz128(rowb));
        LDSM4(ql[s][0], ql[s][1], ql[s][2], ql[s][3], uS + 16384 + swz128(rowb));
    }

    float m0 = -1e30f, m1 = -1e30f, l0 = 0.f, l1 = 0.f;
    float o[8][4];
    #pragma unroll
    for (int j = 0; j < 8; j++)
        #pragma unroll
        for (int f = 0; f < 4; f++) o[j][f] = 0.f;

    for (int kt = 0; kt < N; kt += 64) {
        __syncthreads();
        #pragma unroll
        for (int t = 0; t < 8; t++) {
            int idx = tid + t * 256;
            int arr = idx >> 9;
            int rem = idx & 511;
            int row = rem >> 3, g16 = rem & 7;
            const __nv_bfloat16* gsrc =
                (arr == 0) ? g_kh : (arr == 1) ? g_kl : (arr == 2) ? g_vh : g_vl;
            uint4 val = *((const uint4*)&gsrc[bhbase + (size_t)(kt + row) * DH] + g16);
            *(uint4*)(sm + arr * 8192 + swz128(row * 128 + g16 * 16)) = val;
        }
        __syncthreads();

        float sacc[8][4];
        #pragma unroll
        for (int j = 0; j < 8; j++)
            #pragma unroll
            for (int f = 0; f < 4; f++) sacc[j][f] = 0.f;

        #pragma unroll
        for (int s = 0; s < 4; s++) {
            uint32_t kh[8][2], kl[8][2];
            #pragma unroll
            for (int jp = 0; jp < 4; jp++) {
                const uint32_t rowb = (jp * 16 + b_ti * 8 + r8) * 128 + s * 32 + b_kb;
                LDSM4(kh[2*jp][0], kh[2*jp][1], kh[2*jp+1][0], kh[2*jp+1][1],
                      uS + oKh + swz128(rowb));
                LDSM4(kl[2*jp][0], kl[2*jp][1], kl[2*jp+1][0], kl[2*jp+1][1],
                      uS + oKl + swz128(rowb));
            }
            #pragma unroll
            for (int j = 0; j < 8; j++) {
                MMA16816(sacc[j], qh[s], kh[j]);
                MMA16816(sacc[j], qh[s], kl[j]);
                MMA16816(sacc[j], ql[s], kh[j]);
            }
        }

        float mx0 = -1e30f, mx1 = -1e30f;
        #pragma unroll
        for (int j = 0; j < 8; j++) {
            mx0 = fmaxf(mx0, fmaxf(sacc[j][0], sacc[j][1]));
            mx1 = fmaxf(mx1, fmaxf(sacc[j][2], sacc[j][3]));
        }
        mx0 = fmaxf(mx0, __shfl_xor_sync(0xffffffffu, mx0, 1));
        mx0 = fmaxf(mx0, __shfl_xor_sync(0xffffffffu, mx0, 2));
        mx1 = fmaxf(mx1, __shfl_xor_sync(0xffffffffu, mx1, 1));
        mx1 = fmaxf(mx1, __shfl_xor_sync(0xffffffffu, mx1, 2));
        const float mn0 = fmaxf(m0, mx0), mn1 = fmaxf(m1, mx1);
        const float c0 = __expf(m0 - mn0), c1 = __expf(m1 - mn1);
        m0 = mn0; m1 = mn1;

        float rs0 = 0.f, rs1 = 0.f;
        uint32_t ph[8][2], pl[8][2];
        #pragma unroll
        for (int j = 0; j < 8; j++) {
            float p00 = __expf(sacc[j][0] - mn0);
            float p01 = __expf(sacc[j][1] - mn0);
            float p10 = __expf(sacc[j][2] - mn1);
            float p11 = __expf(sacc[j][3] - mn1);
            rs0 += p00 + p01; rs1 += p10 + p11;
            split2(p00, p01, ph[j][0], pl[j][0]);
            split2(p10, p11, ph[j][1], pl[j][1]);
        }
        rs0 += __shfl_xor_sync(0xffffffffu, rs0, 1);
        rs0 += __shfl_xor_sync(0xffffffffu, rs0, 2);
        rs1 += __shfl_xor_sync(0xffffffffu, rs1, 1);
        rs1 += __shfl_xor_sync(0xffffffffu, rs1, 2);
        l0 = l0 * c0 + rs0;
        l1 = l1 * c1 + rs1;

        #pragma unroll
        for (int j = 0; j < 8; j++) {
            o[j][0] *= c0; o[j][1] *= c0; o[j][2] *= c1; o[j][3] *= c1;
        }

        #pragma unroll
        for (int s = 0; s < 4; s++) {
            uint32_t ah[4] = { ph[2*s][0], ph[2*s][1], ph[2*s+1][0], ph[2*s+1][1] };
            uint32_t al[4] = { pl[2*s][0], pl[2*s][1], pl[2*s+1][0], pl[2*s+1][1] };
            uint32_t vh[8][2], vl[8][2];
            #pragma unroll
            for (int jp = 0; jp < 4; jp++) {
                const int vrow  = s * 16 + (q & 1) * 8 + r8;
                const int vcolb = jp * 32 + (q >> 1) * 16;
                const uint32_t rowb = vrow * 128 + vcolb;
                LDSM4T(vh[2*jp][0], vh[2*jp][1], vh[2*jp+1][0], vh[2*jp+1][1],
                       uS + oVh + swz128(rowb));
                LDSM4T(vl[2*jp][0], vl[2*jp][1], vl[2*jp+1][0], vl[2*jp+1][1],
                       uS + oVl + swz128(rowb));
            }
            #pragma unroll
            for (int j = 0; j < 8; j++) {
                MMA16816(o[j], ah, vh[j]);
                MMA16816(o[j], ah, vl[j]);
                MMA16816(o[j], al, vh[j]);
            }
        }
    }

    // Epilogue: normalize and write SPLIT bf16 merged-heads output.
    const int bb = bh / H, hh = bh % H;
    const float i0 = 1.f / l0, i1 = 1.f / l1;
    const int nr = n0 + wq + (lane >> 2);
    #pragma unroll
    for (int j = 0; j < 8; j++) {
        const int dh = j * 8 + ((lane & 3) << 1);
        uint32_t hv, lv;
        const size_t ix0 = ((size_t)(bb * N + nr)) * D + hh * DH + dh;
        split2(o[j][0] * i0, o[j][1] * i0, hv, lv);
        *(uint32_t*)&g_aoh[ix0] = hv;
        *(uint32_t*)&g_aol[ix0] = lv;
        const size_t ix1 = ((size_t)(bb * N + nr + 8)) * D + hh * DH + dh;
        split2(o[j][2] * i1, o[j][3] * i1, hv, lv);
        *(uint32_t*)&g_aoh[ix1] = hv;
        *(uint32_t*)&g_aol[ix1] = lv;
    }
}

// ---------------------------------------------------------------------------
// kernel_launch. Inputs by element count: x = M*D; weights = D*D in order
// (Wq, Wk, Wv, Wo); mask ignored. Launches only; no driver/attribute APIs.
// ---------------------------------------------------------------------------
extern "C" void kernel_launch(void* const* d_in, const int* in_sizes, int n_in,
                              void* d_out, int out_size) {
    (void)out_size;
    const float* x = nullptr;
    const float* Wt[4] = {nullptr, nullptr, nullptr, nullptr};
    int c = 0;
    for (int i = 0; i < n_in; i++) {
        if (in_sizes[i] == M * D && !x) x = (const float*)d_in[i];
        else if (in_sizes[i] == D * D && c < 4) Wt[c++] = (const float*)d_in[i];
    }
    float* out = (float*)d_out;

    split_all<<<SPLIT_TOTAL / 1024, 256>>>(x, Wt[0], Wt[1], Wt[2], Wt[3]);

    dim3 gg(M / 128, D / 64);   // (64, 16)
    gemm_bf16<<<gg, 256>>>(nullptr, 0.125f, 0);  // Q (1/sqrt(DH) folded)
    gemm_bf16<<<gg, 256>>>(nullptr, 1.0f,   1);  // K
    gemm_bf16<<<gg, 256>>>(nullptr, 1.0f,   2);  // V

    attn_mma<<<dim3(N / 128, B * H), 256>>>();

    gemm_bf16<<<gg, 256>>>(out, 1.0f, 3);        // Wo projection
}

// round 9
// speedup vs baseline: 4.1485x; 1.1191x over previous
#include <cuda_runtime.h>
#include <cuda_bf16.h>
#include <cstdint>

// Problem constants
constexpr int B  = 4;
constexpr int N  = 2048;
constexpr int D  = 1024;
constexpr int H  = 16;
constexpr int DH = 64;
constexpr int M  = B * N;   // 8192

// Scratch (device globals; referenced directly from device code).
__device__ __align__(16) __nv_bfloat16 g_xh[M * D], g_xl[M * D];     // split x
__device__ __align__(16) __nv_bfloat16 g_wh[4 * D * D], g_wl[4 * D * D]; // split weights
__device__ __align__(16) __nv_bfloat16 g_qh[M * D], g_ql[M * D];     // [b,h,n,dh]
__device__ __align__(16) __nv_bfloat16 g_kh[M * D], g_kl[M * D];
__device__ __align__(16) __nv_bfloat16 g_vh[M * D], g_vl[M * D];
__device__ __align__(16) __nv_bfloat16 g_aoh[M * D], g_aol[M * D];   // attn out split [b,n,d]

__device__ __forceinline__ uint32_t smem_u32(const void* p) {
    uint32_t a;
    asm("{ .reg .u64 t; cvta.to.shared.u64 t, %1; cvt.u32.u64 %0, t; }"
        : "=r"(a) : "l"(p));
    return a;
}
__device__ __forceinline__ uint32_t swz128(uint32_t off) {
    return off ^ ((off >> 3) & 0x70);
}

#define LDSM4(r0, r1, r2, r3, a)                                            \
    asm volatile("ldmatrix.sync.aligned.m8n8.x4.shared.b16 "                \
                 "{%0,%1,%2,%3}, [%4];"                                     \
                 : "=r"(r0), "=r"(r1), "=r"(r2), "=r"(r3) : "r"(a))

#define LDSM4T(r0, r1, r2, r3, a)                                           \
    asm volatile("ldmatrix.sync.aligned.m8n8.x4.trans.shared.b16 "          \
                 "{%0,%1,%2,%3}, [%4];"                                     \
                 : "=r"(r0), "=r"(r1), "=r"(r2), "=r"(r3) : "r"(a))

#define MMA16816(c, a, b)                                                   \
    asm volatile("mma.sync.aligned.m16n8k16.row.col.f32.bf16.bf16.f32 "     \
                 "{%0,%1,%2,%3}, {%4,%5,%6,%7}, {%8,%9}, {%0,%1,%2,%3};"    \
                 : "+f"((c)[0]), "+f"((c)[1]), "+f"((c)[2]), "+f"((c)[3])   \
                 : "r"((a)[0]), "r"((a)[1]), "r"((a)[2]), "r"((a)[3]),      \
                   "r"((b)[0]), "r"((b)[1]))

#define CP16(dst, src)                                                      \
    asm volatile("cp.async.cg.shared.global [%0], [%1], 16;"                \
                 :: "r"(dst), "l"(src))
#define CP_COMMIT() asm volatile("cp.async.commit_group;")
#define CP_WAIT(n)  asm volatile("cp.async.wait_group %0;" :: "n"(n))

// Split packed: two fp32 -> bf16x2 hi + bf16x2 lo
__device__ __forceinline__ void split2(float x, float y, uint32_t& h, uint32_t& l) {
    __nv_bfloat162 hv = __floats2bfloat162_rn(x, y);
    float2 hf = __bfloat1622float2(hv);
    __nv_bfloat162 lv = __floats2bfloat162_rn(x - hf.x, y - hf.y);
    h = *(uint32_t*)&hv; l = *(uint32_t*)&lv;
}

// ---------------------------------------------------------------------------
// Elementwise pre-split: x -> g_xh/g_xl ; W0..W3 -> g_wh/g_wl.
// ---------------------------------------------------------------------------
constexpr int SPLIT_TOTAL = M * D + 4 * D * D;

__global__ void __launch_bounds__(256) split_all(
    const float* __restrict__ x,
    const float* __restrict__ w0, const float* __restrict__ w1,
    const float* __restrict__ w2, const float* __restrict__ w3)
{
    const size_t i = ((size_t)blockIdx.x * 256 + threadIdx.x) * 4;
    const float* src;
    __nv_bfloat16 *dh, *dl;
    size_t off;
    if (i < (size_t)M * D) {
        src = x; dh = g_xh; dl = g_xl; off = i;
    } else {
        size_t r = i - (size_t)M * D;
        int wi = (int)(r / (D * D));
        off = r % (D * D);
        src = (wi == 0) ? w0 : (wi == 1) ? w1 : (wi == 2) ? w2 : w3;
        dh = g_wh + (size_t)wi * D * D;
        dl = g_wl + (size_t)wi * D * D;
    }
    float4 v = *(const float4*)(src + off);
    uint32_t h0, l0, h1, l1;
    split2(v.x, v.y, h0, l0);
    split2(v.z, v.w, h1, l1);
    *(uint2*)(dh + off) = make_uint2(h0, h1);
    *(uint2*)(dl + off) = make_uint2(l0, l1);
}

// ---------------------------------------------------------------------------
// bf16 GEMM (NT) with pre-split inputs and cp.async double buffering.
// (unchanged from passing R8 kernel: 145us, tensor 58.5%)
// ---------------------------------------------------------------------------
constexpr int STG = 24576;   // bytes per stage

__device__ __forceinline__ void gemm_load_stage(
    uint32_t smbase, int tid, int m0, int e0, int k0,
    const __nv_bfloat16* Ah, const __nv_bfloat16* Al,
    const __nv_bfloat16* Bh, const __nv_bfloat16* Bl)
{
    #pragma unroll
    for (int t = 0; t < 4; t++) {
        int idx = tid + t * 256;
        int arr = idx >> 9;
        int rem = idx & 511;
        int row = rem >> 2, u = rem & 3;
        const __nv_bfloat16* s = (arr ? Al : Ah) + (size_t)(m0 + row) * D + k0 + u * 8;
        CP16(smbase + swz128(row * 128 + arr * 64 + u * 16), s);
    }
    #pragma unroll
    for (int t = 0; t < 2; t++) {
        int idx = tid + t * 256;
        int arr = idx >> 8;
        int rem = idx & 255;
        int row = rem >> 2, u = rem & 3;
        const __nv_bfloat16* s = (arr ? Bl : Bh) + (size_t)(e0 + row) * D + k0 + u * 8;
        CP16(smbase + 16384 + swz128(row * 128 + arr * 64 + u * 16), s);
    }
}

__global__ void __launch_bounds__(256) gemm_bf16(
    float* __restrict__ Cout, float scale, int mode)
{
    __shared__ __align__(128) char sm[2 * STG];   // 48KB

    const __nv_bfloat16 *Ah, *Al;
    if (mode < 3) { Ah = g_xh; Al = g_xl; }
    else          { Ah = g_aoh; Al = g_aol; }
    const __nv_bfloat16* Bh = g_wh + (size_t)mode * D * D;
    const __nv_bfloat16* Bl = g_wl + (size_t)mode * D * D;
    __nv_bfloat16 *Ch = nullptr, *Cl = nullptr;
    if      (mode == 0) { Ch = g_qh; Cl = g_ql; }
    else if (mode == 1) { Ch = g_kh; Cl = g_kl; }
    else if (mode == 2) { Ch = g_vh; Cl = g_vl; }

    const int tid  = threadIdx.x;
    const int lane = tid & 31;
    const int wid  = tid >> 5;
    const int wm   = (wid >> 1) * 32;
    const int wn   = (wid & 1) * 32;
    const int m0   = blockIdx.x * 128;
    const int e0   = blockIdx.y * 64;

    const uint32_t uS = smem_u32(sm);

    const int q  = lane >> 3;
    const int r8 = lane & 7;
    const int a_row = (q & 1) * 8 + r8;
    const int a_kb  = (q >> 1) * 16;
    const int b_ti  = (q >> 1);
    const int b_kb  = (q & 1) * 16;

    float acc[2][4][4];
    #pragma unroll
    for (int i = 0; i < 2; i++)
        #pragma unroll
        for (int j = 0; j < 4; j++)
            #pragma unroll
            for (int f = 0; f < 4; f++) acc[i][j][f] = 0.f;

    constexpr int NC = D / 32;

    gemm_load_stage(uS, tid, m0, e0, 0, Ah, Al, Bh, Bl);
    CP_COMMIT();

    for (int kc = 0; kc < NC; kc++) {
        if (kc + 1 < NC) {
            gemm_load_stage(uS + ((kc + 1) & 1) * STG, tid, m0, e0, (kc + 1) * 32,
                            Ah, Al, Bh, Bl);
            CP_COMMIT();
            CP_WAIT(1);
        } else {
            CP_WAIT(0);
        }
        __syncthreads();

        const uint32_t uA = uS + (kc & 1) * STG;
        const uint32_t uB = uA + 16384;

        #pragma unroll
        for (int s = 0; s < 2; s++) {
            uint32_t ah[2][4], al[2][4], bh[4][2], bl[4][2];
            #pragma unroll
            for (int i = 0; i < 2; i++) {
                const uint32_t rowb = (wm + i * 16 + a_row) * 128 + s * 32 + a_kb;
                LDSM4(ah[i][0], ah[i][1], ah[i][2], ah[i][3], uA + swz128(rowb));
                LDSM4(al[i][0], al[i][1], al[i][2], al[i][3], uA + swz128(rowb + 64));
            }
            #pragma unroll
            for (int jp = 0; jp < 2; jp++) {
                const uint32_t rowb =
                    (wn + (jp * 2 + b_ti) * 8 + r8) * 128 + s * 32 + b_kb;
                LDSM4(bh[2*jp][0], bh[2*jp][1], bh[2*jp+1][0], bh[2*jp+1][1],
                      uB + swz128(rowb));
                LDSM4(bl[2*jp][0], bl[2*jp][1], bl[2*jp+1][0], bl[2*jp+1][1],
                      uB + swz128(rowb + 64));
            }
            #pragma unroll
            for (int i = 0; i < 2; i++)
                #pragma unroll
                for (int j = 0; j < 4; j++) {
                    MMA16816(acc[i][j], ah[i], bh[j]);
                    MMA16816(acc[i][j], ah[i], bl[j]);
                    MMA16816(acc[i][j], al[i], bh[j]);
                }
        }
        __syncthreads();
    }

    #pragma unroll
    for (int i = 0; i < 2; i++) {
        #pragma unroll
        for (int j = 0; j < 4; j++) {
            const int m = m0 + wm + i * 16 + (lane >> 2);
            const int e = e0 + wn + j * 8 + ((lane & 3) << 1);
            #pragma unroll
            for (int half = 0; half < 2; half++) {
                const int mm = m + half * 8;
                const int bb = mm >> 11;
                const int nn = mm & (N - 1);
                float vx = acc[i][j][2*half + 0] * scale;
                float vy = acc[i][j][2*half + 1] * scale;
                if (mode != 3) {
                    const int h = e >> 6, dh = e & 63;
                    const size_t idx = (((size_t)(bb * H + h)) * N + nn) * DH + dh;
                    uint32_t hv, lv;
                    split2(vx, vy, hv, lv);
                    *(uint32_t*)&Ch[idx] = hv;
                    *(uint32_t*)&Cl[idx] = lv;
                } else {
                    *(float2*)&Cout[(size_t)mm * D + e] = make_float2(vx, vy);
                }
            }
        }
    }
}

// ---------------------------------------------------------------------------
// Flash attention, mma.sync bf16 + split compensation, with PHASE-SPLIT
// cp.async pipelining: K(t+1) prefetched during softmax+PV of tile t;
// V(t+1) prefetched during S of tile t+1. Same 32KB SMEM, loads hidden.
// Commit order: K0,V0,K1,V1,...  wait_group(1) alternately pins K / V done.
// ---------------------------------------------------------------------------
__device__ __forceinline__ void attn_load_K(uint32_t uS, int tid,
                                            size_t bhbase, int kt)
{
    #pragma unroll
    for (int t = 0; t < 4; t++) {
        int idx = tid + t * 256;        // 0..1023
        int arr = idx >> 9;             // 0: Kh, 1: Kl
        int rem = idx & 511;
        int row = rem >> 3, g16 = rem & 7;
        const __nv_bfloat16* s =
            (arr ? g_kl : g_kh) + bhbase + (size_t)(kt + row) * DH + g16 * 8;
        CP16(uS + arr * 8192 + swz128(row * 128 + g16 * 16), s);
    }
}
__device__ __forceinline__ void attn_load_V(uint32_t uS, int tid,
                                            size_t bhbase, int kt)
{
    #pragma unroll
    for (int t = 0; t < 4; t++) {
        int idx = tid + t * 256;
        int arr = idx >> 9;             // 0: Vh, 1: Vl
        int rem = idx & 511;
        int row = rem >> 3, g16 = rem & 7;
        const __nv_bfloat16* s =
            (arr ? g_vl : g_vh) + bhbase + (size_t)(kt + row) * DH + g16 * 8;
        CP16(uS + 16384 + arr * 8192 + swz128(row * 128 + g16 * 16), s);
    }
}

__global__ void __launch_bounds__(256) attn_mma()
{
    __shared__ __align__(128) char sm[32768];
    const uint32_t uS = smem_u32(sm);
    constexpr uint32_t oKh = 0, oKl = 8192, oVh = 16384, oVl = 24576;

    const int tid  = threadIdx.x;
    const int lane = tid & 31;
    const int wid  = tid >> 5;
    const int bh   = blockIdx.y;
    const int n0   = blockIdx.x * 128;
    const int wq   = wid * 16;

    const int q  = lane >> 3;
    const int r8 = lane & 7;
    const int a_row = (q & 1) * 8 + r8;
    const int a_kb  = (q >> 1) * 16;
    const int b_ti  = (q >> 1);
    const int b_kb  = (q & 1) * 16;

    const size_t bhbase = (size_t)bh * N * DH;

    // Stage Q (hi at 0, lo at +16KB) -> register fragments, then free buffer.
    #pragma unroll
    for (int t = 0; t < 4; t++) {
        int idx = tid + t * 256;
        int row = idx >> 3;
        int g16 = idx & 7;
        const size_t src = bhbase + (size_t)(n0 + row) * DH;
        *(uint4*)(sm + swz128(row * 128 + g16 * 16)) =
            *((const uint4*)&g_qh[src] + g16);
        *(uint4*)(sm + 16384 + swz128(row * 128 + g16 * 16)) =
            *((const uint4*)&g_ql[src] + g16);
    }
    __syncthreads();

    uint32_t qh[4][4], ql[4][4];
    #pragma unroll
    for (int s = 0; s < 4; s++) {
        const uint32_t rowb = (wq + a_row) * 128 + s * 32 + a_kb;
        LDSM4(qh[s][0], qh[s][1], qh[s][2], qh[s][3], uS + swz128(rowb));
        LDSM4(ql[s][0], ql[s][1], ql[s][2], ql[s][3], uS + 16384 + swz128(rowb));
    }
    __syncthreads();   // all warps extracted Q before K/V(0) overwrite buffer

    // Prime pipeline: K(0), V(0)
    attn_load_K(uS, tid, bhbase, 0); CP_COMMIT();
    attn_load_V(uS, tid, bhbase, 0); CP_COMMIT();

    float m0 = -1e30f, m1 = -1e30f, l0 = 0.f, l1 = 0.f;
    float o[8][4];
    #pragma unroll
    for (int j = 0; j < 8; j++)
        #pragma unroll
        for (int f = 0; f < 4; f++) o[j][f] = 0.f;

    for (int kt = 0; kt < N; kt += 64) {
        // ---- wait K(kt); V(kt) may still be in flight
        CP_WAIT(1);
        __syncthreads();

        // ---- S = Q @ K^T
        float sacc[8][4];
        #pragma unroll
        for (int j = 0; j < 8; j++)
            #pragma unroll
            for (int f = 0; f < 4; f++) sacc[j][f] = 0.f;

        #pragma unroll
        for (int s = 0; s < 4; s++) {
            uint32_t kh[8][2], kl[8][2];
            #pragma unroll
            for (int jp = 0; jp < 4; jp++) {
                const uint32_t rowb = (jp * 16 + b_ti * 8 + r8) * 128 + s * 32 + b_kb;
                LDSM4(kh[2*jp][0], kh[2*jp][1], kh[2*jp+1][0], kh[2*jp+1][1],
                      uS + oKh + swz128(rowb));
                LDSM4(kl[2*jp][0], kl[2*jp][1], kl[2*jp+1][0], kl[2*jp+1][1],
                      uS + oKl + swz128(rowb));
            }
            #pragma unroll
            for (int j = 0; j < 8; j++) {
                MMA16816(sacc[j], qh[s], kh[j]);
                MMA16816(sacc[j], qh[s], kl[j]);
                MMA16816(sacc[j], ql[s], kh[j]);
            }
        }

        __syncthreads();   // all warps done reading K buffer
        // ---- prefetch K(kt+1) into freed K buffer (overlaps softmax + PV)
        if (kt + 64 < N) attn_load_K(uS, tid, bhbase, kt + 64);
        CP_COMMIT();       // unconditional: keeps group-count invariant

        // ---- online softmax (registers only)
        float mx0 = -1e30f, mx1 = -1e30f;
        #pragma unroll
        for (int j = 0; j < 8; j++) {
            mx0 = fmaxf(mx0, fmaxf(sacc[j][0], sacc[j][1]));
            mx1 = fmaxf(mx1, fmaxf(sacc[j][2], sacc[j][3]));
        }
        mx0 = fmaxf(mx0, __shfl_xor_sync(0xffffffffu, mx0, 1));
        mx0 = fmaxf(mx0, __shfl_xor_sync(0xffffffffu, mx0, 2));
        mx1 = fmaxf(mx1, __shfl_xor_sync(0xffffffffu, mx1, 1));
        mx1 = fmaxf(mx1, __shfl_xor_sync(0xffffffffu, mx1, 2));
        const float mn0 = fmaxf(m0, mx0), mn1 = fmaxf(m1, mx1);
        const float c0 = __expf(m0 - mn0), c1 = __expf(m1 - mn1);
        m0 = mn0; m1 = mn1;

        float rs0 = 0.f, rs1 = 0.f;
        uint32_t ph[8][2], pl[8][2];
        #pragma unroll
        for (int j = 0; j < 8; j++) {
            float p00 = __expf(sacc[j][0] - mn0);
            float p01 = __expf(sacc[j][1] - mn0);
            float p10 = __expf(sacc[j][2] - mn1);
            float p11 = __expf(sacc[j][3] - mn1);
            rs0 += p00 + p01; rs1 += p10 + p11;
            split2(p00, p01, ph[j][0], pl[j][0]);
            split2(p10, p11, ph[j][1], pl[j][1]);
        }
        rs0 += __shfl_xor_sync(0xffffffffu, rs0, 1);
        rs0 += __shfl_xor_sync(0xffffffffu, rs0, 2);
        rs1 += __shfl_xor_sync(0xffffffffu, rs1, 1);
        rs1 += __shfl_xor_sync(0xffffffffu, rs1, 2);
        l0 = l0 * c0 + rs0;
        l1 = l1 * c1 + rs1;

        #pragma unroll
        for (int j = 0; j < 8; j++) {
            o[j][0] *= c0; o[j][1] *= c0; o[j][2] *= c1; o[j][3] *= c1;
        }

        // ---- wait V(kt); K(kt+1) may still be in flight
        CP_WAIT(1);
        __syncthreads();

        // ---- O += P @ V
        #pragma unroll
        for (int s = 0; s < 4; s++) {
            uint32_t ah[4] = { ph[2*s][0], ph[2*s][1], ph[2*s+1][0], ph[2*s+1][1] };
            uint32_t al[4] = { pl[2*s][0], pl[2*s][1], pl[2*s+1][0], pl[2*s+1][1] };
            uint32_t vh[8][2], vl[8][2];
            #pragma unroll
            for (int jp = 0; jp < 4; jp++) {
                const int vrow  = s * 16 + (q & 1) * 8 + r8;
                const int vcolb = jp * 32 + (q >> 1) * 16;
                const uint32_t rowb = vrow * 128 + vcolb;
                LDSM4T(vh[2*jp][0], vh[2*jp][1], vh[2*jp+1][0], vh[2*jp+1][1],
                       uS + oVh + swz128(rowb));
                LDSM4T(vl[2*jp][0], vl[2*jp][1], vl[2*jp+1][0], vl[2*jp+1][1],
                       uS + oVl + swz128(rowb));
            }
            #pragma unroll
            for (int j = 0; j < 8; j++) {
                MMA16816(o[j], ah, vh[j]);
                MMA16816(o[j], ah, vl[j]);
                MMA16816(o[j], al, vh[j]);
            }
        }

        __syncthreads();   // all warps done reading V buffer
        // ---- prefetch V(kt+1) into freed V buffer (overlaps next S)
        if (kt + 64 < N) attn_load_V(uS, tid, bhbase, kt + 64);
        CP_COMMIT();
    }

    // Epilogue: normalize, write split bf16 merged-heads output.
    const int bb = bh / H, hh = bh % H;
    const float i0 = 1.f / l0, i1 = 1.f / l1;
    const int nr = n0 + wq + (lane >> 2);
    #pragma unroll
    for (int j = 0; j < 8; j++) {
        const int dh = j * 8 + ((lane & 3) << 1);
        uint32_t hv, lv;
        const size_t ix0 = ((size_t)(bb * N + nr)) * D + hh * DH + dh;
        split2(o[j][0] * i0, o[j][1] * i0, hv, lv);
        *(uint32_t*)&g_aoh[ix0] = hv;
        *(uint32_t*)&g_aol[ix0] = lv;
        const size_t ix1 = ((size_t)(bb * N + nr + 8)) * D + hh * DH + dh;
        split2(o[j][2] * i1, o[j][3] * i1, hv, lv);
        *(uint32_t*)&g_aoh[ix1] = hv;
        *(uint32_t*)&g_aol[ix1] = lv;
    }
}

// ---------------------------------------------------------------------------
// kernel_launch. Inputs by element count: x = M*D; weights = D*D in order
// (Wq, Wk, Wv, Wo); mask ignored. Launches only; no driver/attribute APIs.
// ---------------------------------------------------------------------------
extern "C" void kernel_launch(void* const* d_in, const int* in_sizes, int n_in,
                              void* d_out, int out_size) {
    (void)out_size;
    const float* x = nullptr;
    const float* Wt[4] = {nullptr, nullptr, nullptr, nullptr};
    int c = 0;
    for (int i = 0; i < n_in; i++) {
        if (in_sizes[i] == M * D && !x) x = (const float*)d_in[i];
        else if (in_sizes[i] == D * D && c < 4) Wt[c++] = (const float*)d_in[i];
    }
    float* out = (float*)d_out;

    split_all<<<SPLIT_TOTAL / 1024, 256>>>(x, Wt[0], Wt[1], Wt[2], Wt[3]);

    dim3 gg(M / 128, D / 64);   // (64, 16)
    gemm_bf16<<<gg, 256>>>(nullptr, 0.125f, 0);  // Q (1/sqrt(DH) folded)
    gemm_bf16<<<gg, 256>>>(nullptr, 1.0f,   1);  // K
    gemm_bf16<<<gg, 256>>>(nullptr, 1.0f,   2);  // V

    attn_mma<<<dim3(N / 128, B * H), 256>>>();

    gemm_bf16<<<gg, 256>>>(out, 1.0f, 3);        // Wo projection
}

// round 10
// speedup vs baseline: 4.2990x; 1.0363x over previous
#include <cuda_runtime.h>
#include <cuda_bf16.h>
#include <cstdint>

// Problem constants
constexpr int B  = 4;
constexpr int N  = 2048;
constexpr int D  = 1024;
constexpr int H  = 16;
constexpr int DH = 64;
constexpr int M  = B * N;   // 8192

// Scratch (device globals; referenced directly from device code).
__device__ __align__(16) __nv_bfloat16 g_xh[M * D], g_xl[M * D];     // split x
__device__ __align__(16) __nv_bfloat16 g_wh[4 * D * D], g_wl[4 * D * D]; // split weights
__device__ __align__(16) __nv_bfloat16 g_qh[M * D], g_ql[M * D];     // [b,h,n,dh]
__device__ __align__(16) __nv_bfloat16 g_kh[M * D], g_kl[M * D];
__device__ __align__(16) __nv_bfloat16 g_vh[M * D], g_vl[M * D];
__device__ __align__(16) __nv_bfloat16 g_aoh[M * D], g_aol[M * D];   // attn out split [b,n,d]

__device__ __forceinline__ uint32_t smem_u32(const void* p) {
    uint32_t a;
    asm("{ .reg .u64 t; cvta.to.shared.u64 t, %1; cvt.u32.u64 %0, t; }"
        : "=r"(a) : "l"(p));
    return a;
}
__device__ __forceinline__ uint32_t swz128(uint32_t off) {
    return off ^ ((off >> 3) & 0x70);
}

#define LDSM4(r0, r1, r2, r3, a)                                            \
    asm volatile("ldmatrix.sync.aligned.m8n8.x4.shared.b16 "                \
                 "{%0,%1,%2,%3}, [%4];"                                     \
                 : "=r"(r0), "=r"(r1), "=r"(r2), "=r"(r3) : "r"(a))

#define LDSM4T(r0, r1, r2, r3, a)                                           \
    asm volatile("ldmatrix.sync.aligned.m8n8.x4.trans.shared.b16 "          \
                 "{%0,%1,%2,%3}, [%4];"                                     \
                 : "=r"(r0), "=r"(r1), "=r"(r2), "=r"(r3) : "r"(a))

#define MMA16816(c, a, b)                                                   \
    asm volatile("mma.sync.aligned.m16n8k16.row.col.f32.bf16.bf16.f32 "     \
                 "{%0,%1,%2,%3}, {%4,%5,%6,%7}, {%8,%9}, {%0,%1,%2,%3};"    \
                 : "+f"((c)[0]), "+f"((c)[1]), "+f"((c)[2]), "+f"((c)[3])   \
                 : "r"((a)[0]), "r"((a)[1]), "r"((a)[2]), "r"((a)[3]),      \
                   "r"((b)[0]), "r"((b)[1]))

#define CP16(dst, src)                                                      \
    asm volatile("cp.async.cg.shared.global [%0], [%1], 16;"                \
                 :: "r"(dst), "l"(src))
#define CP_COMMIT() asm volatile("cp.async.commit_group;")
#define CP_WAIT(n)  asm volatile("cp.async.wait_group %0;" :: "n"(n))

// Split packed: two fp32 -> bf16x2 hi + bf16x2 lo
__device__ __forceinline__ void split2(float x, float y, uint32_t& h, uint32_t& l) {
    __nv_bfloat162 hv = __floats2bfloat162_rn(x, y);
    float2 hf = __bfloat1622float2(hv);
    __nv_bfloat162 lv = __floats2bfloat162_rn(x - hf.x, y - hf.y);
    h = *(uint32_t*)&hv; l = *(uint32_t*)&lv;
}

// ---------------------------------------------------------------------------
// Elementwise pre-split: x -> g_xh/g_xl ; W0..W3 -> g_wh/g_wl.
// ---------------------------------------------------------------------------
constexpr int SPLIT_TOTAL = M * D + 4 * D * D;

__global__ void __launch_bounds__(256) split_all(
    const float* __restrict__ x,
    const float* __restrict__ w0, const float* __restrict__ w1,
    const float* __restrict__ w2, const float* __restrict__ w3)
{
    const size_t i = ((size_t)blockIdx.x * 256 + threadIdx.x) * 4;
    const float* src;
    __nv_bfloat16 *dh, *dl;
    size_t off;
    if (i < (size_t)M * D) {
        src = x; dh = g_xh; dl = g_xl; off = i;
    } else {
        size_t r = i - (size_t)M * D;
        int wi = (int)(r / (D * D));
        off = r % (D * D);
        src = (wi == 0) ? w0 : (wi == 1) ? w1 : (wi == 2) ? w2 : w3;
        dh = g_wh + (size_t)wi * D * D;
        dl = g_wl + (size_t)wi * D * D;
    }
    float4 v = *(const float4*)(src + off);
    uint32_t h0, l0, h1, l1;
    split2(v.x, v.y, h0, l0);
    split2(v.z, v.w, h1, l1);
    *(uint2*)(dh + off) = make_uint2(h0, h1);
    *(uint2*)(dl + off) = make_uint2(l0, l1);
}

// ---------------------------------------------------------------------------
// bf16 GEMM (NT), pre-split inputs, NS-stage cp.async pipeline (templated),
// ONE __syncthreads per chunk:  wait(NS-2) -> sync -> issue load -> compute.
// CTA tile 128(M) x 64(N), BK=32.  Stage = A 16KB + B 8KB = 24KB.
// QKV: grid.z selects mode 0/1/2 (shared A in L2). Wo: mode_base = 3.
// ---------------------------------------------------------------------------
constexpr int STG = 24576;   // bytes per stage

__device__ __forceinline__ void gemm_load_stage(
    uint32_t smbase, int tid, int m0, int e0, int k0,
    const __nv_bfloat16* Ah, const __nv_bfloat16* Al,
    const __nv_bfloat16* Bh, const __nv_bfloat16* Bl)
{
    #pragma unroll
    for (int t = 0; t < 4; t++) {
        int idx = tid + t * 256;
        int arr = idx >> 9;
        int rem = idx & 511;
        int row = rem >> 2, u = rem & 3;
        const __nv_bfloat16* s = (arr ? Al : Ah) + (size_t)(m0 + row) * D + k0 + u * 8;
        CP16(smbase + swz128(row * 128 + arr * 64 + u * 16), s);
    }
    #pragma unroll
    for (int t = 0; t < 2; t++) {
        int idx = tid + t * 256;
        int arr = idx >> 8;
        int rem = idx & 255;
        int row = rem >> 2, u = rem & 3;
        const __nv_bfloat16* s = (arr ? Bl : Bh) + (size_t)(e0 + row) * D + k0 + u * 8;
        CP16(smbase + 16384 + swz128(row * 128 + arr * 64 + u * 16), s);
    }
}

template <int NS>
__global__ void __launch_bounds__(256) gemm_pipe(
    float* __restrict__ Cout, int mode_base)
{
    extern __shared__ __align__(128) char sm[];

    const int mode = mode_base + blockIdx.z;
    const float scale = (mode == 0) ? 0.125f : 1.0f;

    const __nv_bfloat16 *Ah, *Al;
    if (mode < 3) { Ah = g_xh; Al = g_xl; }
    else          { Ah = g_aoh; Al = g_aol; }
    const __nv_bfloat16* Bh = g_wh + (size_t)mode * D * D;
    const __nv_bfloat16* Bl = g_wl + (size_t)mode * D * D;
    __nv_bfloat16 *Ch = nullptr, *Cl = nullptr;
    if      (mode == 0) { Ch = g_qh; Cl = g_ql; }
    else if (mode == 1) { Ch = g_kh; Cl = g_kl; }
    else if (mode == 2) { Ch = g_vh; Cl = g_vl; }

    const int tid  = threadIdx.x;
    const int lane = tid & 31;
    const int wid  = tid >> 5;
    const int wm   = (wid >> 1) * 32;
    const int wn   = (wid & 1) * 32;
    const int m0   = blockIdx.x * 128;
    const int e0   = blockIdx.y * 64;

    const uint32_t uS = smem_u32(sm);

    const int q  = lane >> 3;
    const int r8 = lane & 7;
    const int a_row = (q & 1) * 8 + r8;
    const int a_kb  = (q >> 1) * 16;
    const int b_ti  = (q >> 1);
    const int b_kb  = (q & 1) * 16;

    float acc[2][4][4];
    #pragma unroll
    for (int i = 0; i < 2; i++)
        #pragma unroll
        for (int j = 0; j < 4; j++)
            #pragma unroll
            for (int f = 0; f < 4; f++) acc[i][j][f] = 0.f;

    constexpr int NC = D / 32;   // 32

    // Prologue: stages 0 .. NS-2
    #pragma unroll
    for (int s = 0; s < NS - 1; s++) {
        gemm_load_stage(uS + s * STG, tid, m0, e0, s * 32, Ah, Al, Bh, Bl);
        CP_COMMIT();
    }

    for (int kc = 0; kc < NC; kc++) {
        CP_WAIT(NS - 2);     // stage kc resident
        __syncthreads();     // also: all warps done computing stage kc-1

        const int kn = kc + NS - 1;
        if (kn < NC)
            gemm_load_stage(uS + (kn % NS) * STG, tid, m0, e0, kn * 32,
                            Ah, Al, Bh, Bl);
        CP_COMMIT();         // unconditional: group-count invariant

        const uint32_t uA = uS + (kc % NS) * STG;
        const uint32_t uB = uA + 16384;

        #pragma unroll
        for (int s = 0; s < 2; s++) {
            uint32_t ah[2][4], al[2][4], bh[4][2], bl[4][2];
            #pragma unroll
            for (int i = 0; i < 2; i++) {
                const uint32_t rowb = (wm + i * 16 + a_row) * 128 + s * 32 + a_kb;
                LDSM4(ah[i][0], ah[i][1], ah[i][2], ah[i][3], uA + swz128(rowb));
                LDSM4(al[i][0], al[i][1], al[i][2], al[i][3], uA + swz128(rowb + 64));
            }
            #pragma unroll
            for (int jp = 0; jp < 2; jp++) {
                const uint32_t rowb =
                    (wn + (jp * 2 + b_ti) * 8 + r8) * 128 + s * 32 + b_kb;
                LDSM4(bh[2*jp][0], bh[2*jp][1], bh[2*jp+1][0], bh[2*jp+1][1],
                      uB + swz128(rowb));
                LDSM4(bl[2*jp][0], bl[2*jp][1], bl[2*jp+1][0], bl[2*jp+1][1],
                      uB + swz128(rowb + 64));
            }
            #pragma unroll
            for (int i = 0; i < 2; i++)
                #pragma unroll
                for (int j = 0; j < 4; j++) {
                    MMA16816(acc[i][j], ah[i], bh[j]);
                    MMA16816(acc[i][j], ah[i], bl[j]);
                    MMA16816(acc[i][j], al[i], bh[j]);
                }
        }
    }

    // Epilogue
    #pragma unroll
    for (int i = 0; i < 2; i++) {
        #pragma unroll
        for (int j = 0; j < 4; j++) {
            const int m = m0 + wm + i * 16 + (lane >> 2);
            const int e = e0 + wn + j * 8 + ((lane & 3) << 1);
            #pragma unroll
            for (int half = 0; half < 2; half++) {
                const int mm = m + half * 8;
                const int bb = mm >> 11;
                const int nn = mm & (N - 1);
                float vx = acc[i][j][2*half + 0] * scale;
                float vy = acc[i][j][2*half + 1] * scale;
                if (mode != 3) {
                    const int h = e >> 6, dh = e & 63;
                    const size_t idx = (((size_t)(bb * H + h)) * N + nn) * DH + dh;
                    uint32_t hv, lv;
                    split2(vx, vy, hv, lv);
                    *(uint32_t*)&Ch[idx] = hv;
                    *(uint32_t*)&Cl[idx] = lv;
                } else {
                    *(float2*)&Cout[(size_t)mm * D + e] = make_float2(vx, vy);
                }
            }
        }
    }
}

// ---------------------------------------------------------------------------
// Flash attention, mma.sync bf16 + split compensation, phase-split cp.async
// pipelining (unchanged from passing R9 kernel: ~510us).
// ---------------------------------------------------------------------------
__device__ __forceinline__ void attn_load_K(uint32_t uS, int tid,
                                            size_t bhbase, int kt)
{
    #pragma unroll
    for (int t = 0; t < 4; t++) {
        int idx = tid + t * 256;
        int arr = idx >> 9;
        int rem = idx & 511;
        int row = rem >> 3, g16 = rem & 7;
        const __nv_bfloat16* s =
            (arr ? g_kl : g_kh) + bhbase + (size_t)(kt + row) * DH + g16 * 8;
        CP16(uS + arr * 8192 + swz128(row * 128 + g16 * 16), s);
    }
}
__device__ __forceinline__ void attn_load_V(uint32_t uS, int tid,
                                            size_t bhbase, int kt)
{
    #pragma unroll
    for (int t = 0; t < 4; t++) {
        int idx = tid + t * 256;
        int arr = idx >> 9;
        int rem = idx & 511;
        int row = rem >> 3, g16 = rem & 7;
        const __nv_bfloat16* s =
            (arr ? g_vl : g_vh) + bhbase + (size_t)(kt + row) * DH + g16 * 8;
        CP16(uS + 16384 + arr * 8192 + swz128(row * 128 + g16 * 16), s);
    }
}

__global__ void __launch_bounds__(256) attn_mma()
{
    __shared__ __align__(128) char sm[32768];
    const uint32_t uS = smem_u32(sm);
    constexpr uint32_t oKh = 0, oKl = 8192, oVh = 16384, oVl = 24576;

    const int tid  = threadIdx.x;
    const int lane = tid & 31;
    const int wid  = tid >> 5;
    const int bh   = blockIdx.y;
    const int n0   = blockIdx.x * 128;
    const int wq   = wid * 16;

    const int q  = lane >> 3;
    const int r8 = lane & 7;
    const int a_row = (q & 1) * 8 + r8;
    const int a_kb  = (q >> 1) * 16;
    const int b_ti  = (q >> 1);
    const int b_kb  = (q & 1) * 16;

    const size_t bhbase = (size_t)bh * N * DH;

    // Stage Q (hi at 0, lo at +16KB) -> register fragments, then free buffer.
    #pragma unroll
    for (int t = 0; t < 4; t++) {
        int idx = tid + t * 256;
        int row = idx >> 3;
        int g16 = idx & 7;
        const size_t src = bhbase + (size_t)(n0 + row) * DH;
        *(uint4*)(sm + swz128(row * 128 + g16 * 16)) =
            *((const uint4*)&g_qh[src] + g16);
        *(uint4*)(sm + 16384 + swz128(row * 128 + g16 * 16)) =
            *((const uint4*)&g_ql[src] + g16);
    }
    __syncthreads();

    uint32_t qh[4][4], ql[4][4];
    #pragma unroll
    for (int s = 0; s < 4; s++) {
        const uint32_t rowb = (wq + a_row) * 128 + s * 32 + a_kb;
        LDSM4(qh[s][0], qh[s][1], qh[s][2], qh[s][3], uS + swz128(rowb));
        LDSM4(ql[s][0], ql[s][1], ql[s][2], ql[s][3], uS + 16384 + swz128(rowb));
    }
    __syncthreads();

    attn_load_K(uS, tid, bhbase, 0); CP_COMMIT();
    attn_load_V(uS, tid, bhbase, 0); CP_COMMIT();

    float m0 = -1e30f, m1 = -1e30f, l0 = 0.f, l1 = 0.f;
    float o[8][4];
    #pragma unroll
    for (int j = 0; j < 8; j++)
        #pragma unroll
        for (int f = 0; f < 4; f++) o[j][f] = 0.f;

    for (int kt = 0; kt < N; kt += 64) {
        CP_WAIT(1);
        __syncthreads();

        float sacc[8][4];
        #pragma unroll
        for (int j = 0; j < 8; j++)
            #pragma unroll
            for (int f = 0; f < 4; f++) sacc[j][f] = 0.f;

        #pragma unroll
        for (int s = 0; s < 4; s++) {
            uint32_t kh[8][2], kl[8][2];
            #pragma unroll
            for (int jp = 0; jp < 4; jp++) {
                const uint32_t rowb = (jp * 16 + b_ti * 8 + r8) * 128 + s * 32 + b_kb;
                LDSM4(kh[2*jp][0], kh[2*jp][1], kh[2*jp+1][0], kh[2*jp+1][1],
                      uS + oKh + swz128(rowb));
                LDSM4(kl[2*jp][0], kl[2*jp][1], kl[2*jp+1][0], kl[2*jp+1][1],
                      uS + oKl + swz128(rowb));
            }
            #pragma unroll
            for (int j = 0; j < 8; j++) {
                MMA16816(sacc[j], qh[s], kh[j]);
                MMA16816(sacc[j], qh[s], kl[j]);
                MMA16816(sacc[j], ql[s], kh[j]);
            }
        }

        __syncthreads();
        if (kt + 64 < N) attn_load_K(uS, tid, bhbase, kt + 64);
        CP_COMMIT();

        float mx0 = -1e30f, mx1 = -1e30f;
        #pragma unroll
        for (int j = 0; j < 8; j++) {
            mx0 = fmaxf(mx0, fmaxf(sacc[j][0], sacc[j][1]));
            mx1 = fmaxf(mx1, fmaxf(sacc[j][2], sacc[j][3]));
        }
        mx0 = fmaxf(mx0, __shfl_xor_sync(0xffffffffu, mx0, 1));
        mx0 = fmaxf(mx0, __shfl_xor_sync(0xffffffffu, mx0, 2));
        mx1 = fmaxf(mx1, __shfl_xor_sync(0xffffffffu, mx1, 1));
        mx1 = fmaxf(mx1, __shfl_xor_sync(0xffffffffu, mx1, 2));
        const float mn0 = fmaxf(m0, mx0), mn1 = fmaxf(m1, mx1);
        const float c0 = __expf(m0 - mn0), c1 = __expf(m1 - mn1);
        m0 = mn0; m1 = mn1;

        float rs0 = 0.f, rs1 = 0.f;
        uint32_t ph[8][2], pl[8][2];
        #pragma unroll
        for (int j = 0; j < 8; j++) {
            float p00 = __expf(sacc[j][0] - mn0);
            float p01 = __expf(sacc[j][1] - mn0);
            float p10 = __expf(sacc[j][2] - mn1);
            float p11 = __expf(sacc[j][3] - mn1);
            rs0 += p00 + p01; rs1 += p10 + p11;
            split2(p00, p01, ph[j][0], pl[j][0]);
            split2(p10, p11, ph[j][1], pl[j][1]);
        }
        rs0 += __shfl_xor_sync(0xffffffffu, rs0, 1);
        rs0 += __shfl_xor_sync(0xffffffffu, rs0, 2);
        rs1 += __shfl_xor_sync(0xffffffffu, rs1, 1);
        rs1 += __shfl_xor_sync(0xffffffffu, rs1, 2);
        l0 = l0 * c0 + rs0;
        l1 = l1 * c1 + rs1;

        #pragma unroll
        for (int j = 0; j < 8; j++) {
            o[j][0] *= c0; o[j][1] *= c0; o[j][2] *= c1; o[j][3] *= c1;
        }

        CP_WAIT(1);
        __syncthreads();

        #pragma unroll
        for (int s = 0; s < 4; s++) {
            uint32_t ah[4] = { ph[2*s][0], ph[2*s][1], ph[2*s+1][0], ph[2*s+1][1] };
            uint32_t al[4] = { pl[2*s][0], pl[2*s][1], pl[2*s+1][0], pl[2*s+1][1] };
            uint32_t vh[8][2], vl[8][2];
            #pragma unroll
            for (int jp = 0; jp < 4; jp++) {
                const int vrow  = s * 16 + (q & 1) * 8 + r8;
                const int vcolb = jp * 32 + (q >> 1) * 16;
                const uint32_t rowb = vrow * 128 + vcolb;
                LDSM4T(vh[2*jp][0], vh[2*jp][1], vh[2*jp+1][0], vh[2*jp+1][1],
                       uS + oVh + swz128(rowb));
                LDSM4T(vl[2*jp][0], vl[2*jp][1], vl[2*jp+1][0], vl[2*jp+1][1],
                       uS + oVl + swz128(rowb));
            }
            #pragma unroll
            for (int j = 0; j < 8; j++) {
                MMA16816(o[j], ah, vh[j]);
                MMA16816(o[j], ah, vl[j]);
                MMA16816(o[j], al, vh[j]);
            }
        }

        __syncthreads();
        if (kt + 64 < N) attn_load_V(uS, tid, bhbase, kt + 64);
        CP_COMMIT();
    }

    const int bb = bh / H, hh = bh % H;
    const float i0 = 1.f / l0, i1 = 1.f / l1;
    const int nr = n0 + wq + (lane >> 2);
    #pragma unroll
    for (int j = 0; j < 8; j++) {
        const int dh = j * 8 + ((lane & 3) << 1);
        uint32_t hv, lv;
        const size_t ix0 = ((size_t)(bb * N + nr)) * D + hh * DH + dh;
        split2(o[j][0] * i0, o[j][1] * i0, hv, lv);
        *(uint32_t*)&g_aoh[ix0] = hv;
        *(uint32_t*)&g_aol[ix0] = lv;
        const size_t ix1 = ((size_t)(bb * N + nr + 8)) * D + hh * DH + dh;
        split2(o[j][2] * i1, o[j][3] * i1, hv, lv);
        *(uint32_t*)&g_aoh[ix1] = hv;
        *(uint32_t*)&g_aol[ix1] = lv;
    }
}

// ---------------------------------------------------------------------------
// kernel_launch. Inputs by element count: x = M*D; weights = D*D in order
// (Wq, Wk, Wv, Wo); mask ignored.
// 3-stage pipeline needs 72KB dynamic smem (cudaFuncSetAttribute). If the
// attribute call fails in this environment, fall back to the proven 2-stage
// 48KB-dynamic path (no opt-in needed). Deterministic either way.
// ---------------------------------------------------------------------------
extern "C" void kernel_launch(void* const* d_in, const int* in_sizes, int n_in,
                              void* d_out, int out_size) {
    (void)out_size;
    const float* x = nullptr;
    const float* Wt[4] = {nullptr, nullptr, nullptr, nullptr};
    int c = 0;
    for (int i = 0; i < n_in; i++) {
        if (in_sizes[i] == M * D && !x) x = (const float*)d_in[i];
        else if (in_sizes[i] == D * D && c < 4) Wt[c++] = (const float*)d_in[i];
    }
    float* out = (float*)d_out;

    split_all<<<SPLIT_TOTAL / 1024, 256>>>(x, Wt[0], Wt[1], Wt[2], Wt[3]);

    const dim3 gQKV(M / 128, D / 64, 3);   // (64, 16, 3) merged Q/K/V
    const dim3 gWo (M / 128, D / 64, 1);

    cudaError_t attr_ok = cudaFuncSetAttribute(
        gemm_pipe<3>, cudaFuncAttributeMaxDynamicSharedMemorySize, 3 * STG);

    if (attr_ok == cudaSuccess) {
        gemm_pipe<3><<<gQKV, 256, 3 * STG>>>(nullptr, 0);
        attn_mma<<<dim3(N / 128, B * H), 256>>>();
        gemm_pipe<3><<<gWo, 256, 3 * STG>>>(out, 3);
    } else {
        (void)cudaGetLastError();   // clear sticky error from failed attribute
        gemm_pipe<2><<<gQKV, 256, 2 * STG>>>(nullptr, 0);
        attn_mma<<<dim3(N / 128, B * H), 256>>>();
        gemm_pipe<2><<<gWo, 256, 2 * STG>>>(out, 3);
    }
}